// round 12
// baseline (speedup 1.0000x reference)
#include <cuda_runtime.h>
#include <cuda_fp16.h>

// ---------------------------------------------------------------------------
// UNetV2 on GB300: single persistent mega-kernel, software grid barriers.
// Phases: zero+convert | build_rb | nb(lat)+nb(bot) | epi1 | nb(h1) | epi2 |
//         nb(h2) | epi3 | nb(h3) | epi4->out
// nb = FMA f32x2 gather-GEMM + coalesced fp16x2 atomics (R10 form)
// epi = HMMA center tap -> smem transpose -> lane=voxel coalesced IO (R11 form)
// ---------------------------------------------------------------------------

#define MAXN 500000
#define NC   32
#define SEG  16384
#define NBK  26
#define BLKSEG 64
#define ASTRIDE ((size_t)(MAXN + 1) * NC)
#define ROWB 80
#define WSPAN (3 * 32 * ROWB)
#define DYNSM (8 * WSPAN)            // 61440 B

static __device__ __align__(16) __half g_acc[4 * ASTRIDE];
static __device__ __align__(16) __half g_h1[MAXN * NC];
static __device__ __align__(16) __half g_h2[MAXN * NC];
static __device__ __align__(16) __half g_h3[MAXN * NC];
static __device__ __align__(16) __half g_hlat[MAXN * NC];
static __device__ __align__(16) __half g_hbot[MAXN * NC];
static __device__ int2   g_rb[NBK * SEG];
static __device__ int    g_kcnt[32];
static __device__ unsigned g_count = 0;
static __device__ unsigned g_sense = 0;

typedef unsigned long long u64;

__device__ __forceinline__ u64 splat2(float a) {
    u64 r; asm("mov.b64 %0, {%1, %1};" : "=l"(r) : "f"(a)); return r;
}
__device__ __forceinline__ u64 pack2(float a, float b) {
    u64 r; asm("mov.b64 %0, {%1, %2};" : "=l"(r) : "f"(a), "f"(b)); return r;
}
__device__ __forceinline__ void fma2(u64& d, u64 a, u64 b) {
    asm("fma.rn.f32x2 %0, %1, %2, %3;" : "=l"(d) : "l"(a), "l"(b), "l"(d));
}
__device__ __forceinline__ float2 unpack2(u64 a) {
    float2 r; asm("mov.b64 {%0, %1}, %2;" : "=f"(r.x), "=f"(r.y) : "l"(a)); return r;
}
__device__ __forceinline__ unsigned cvt_h2(float lo, float hi) {
    unsigned r;
    asm("cvt.rn.f16x2.f32 %0, %1, %2;" : "=r"(r) : "f"(hi), "f"(lo));
    return r;
}
__device__ __forceinline__ float2 h2f(unsigned u) {
    return __half22float2(*(__half2*)&u);
}
__device__ __forceinline__ void redadd_h2(__half* p, unsigned hv) {
    asm volatile("red.global.add.noftz.f16x2 [%0], %1;" :: "l"(p), "r"(hv) : "memory");
}

// ---------------------------------------------------------------------------
// software grid barrier (sense-reversing, self-resetting)
// ---------------------------------------------------------------------------
__device__ __forceinline__ void gridbar(int nblk) {
    __syncthreads();
    if (threadIdx.x == 0) {
        __threadfence();
        unsigned s = *(volatile unsigned*)&g_sense;
        if (atomicInc(&g_count, (unsigned)(nblk - 1)) == (unsigned)(nblk - 1)) {
            atomicAdd(&g_sense, 1u);
        } else {
            while (*(volatile unsigned*)&g_sense == s) __nanosleep(64);
        }
        __threadfence();
    }
    __syncthreads();
}

// ---------------------------------------------------------------------------
// HMMA helpers
// ---------------------------------------------------------------------------
__device__ __forceinline__ void stage_row(char* wbase, int r, const __half* row) {
    const uint4* s = (const uint4*)row;
    int sw = (r >> 3) & 3;
    char* rb = wbase + r * ROWB;
    #pragma unroll
    for (int c = 0; c < 4; ++c)
        *(uint4*)(rb + ((c ^ sw) << 4)) = __ldg(s + c);
}
__device__ __forceinline__ void ldmA(unsigned a[4], const char* wbase, int mt,
                                     int kb, int lane) {
    int r  = mt * 16 + (lane & 15);
    int lc = 2 * kb + (lane >> 4);
    unsigned addr = (unsigned)__cvta_generic_to_shared(
        wbase + r * ROWB + ((lc ^ ((r >> 3) & 3)) << 4));
    asm volatile("ldmatrix.sync.aligned.m8n8.x4.shared.b16 {%0,%1,%2,%3}, [%4];"
                 : "=r"(a[0]), "=r"(a[1]), "=r"(a[2]), "=r"(a[3]) : "r"(addr));
}
__device__ __forceinline__ void mma16816(float d[4], const unsigned a[4],
                                         const unsigned b[2]) {
    asm volatile(
        "mma.sync.aligned.m16n8k16.row.col.f32.f16.f16.f32 "
        "{%0,%1,%2,%3},{%4,%5,%6,%7},{%8,%9},{%0,%1,%2,%3};"
        : "+f"(d[0]), "+f"(d[1]), "+f"(d[2]), "+f"(d[3])
        : "r"(a[0]), "r"(a[1]), "r"(a[2]), "r"(a[3]), "r"(b[0]), "r"(b[1]));
}
__device__ __forceinline__ void buildB(unsigned bf[4][2][2], const float* Wk,
                                       int lane) {
    int g = lane >> 2, t = lane & 3;
    #pragma unroll
    for (int nb = 0; nb < 4; ++nb) {
        int nn = nb * 8 + g;
        #pragma unroll
        for (int kb = 0; kb < 2; ++kb) {
            int k0 = 16 * kb + 2 * t;
            bf[nb][kb][0] = cvt_h2(__ldg(Wk + k0 * 32 + nn),
                                   __ldg(Wk + (k0 + 1) * 32 + nn));
            bf[nb][kb][1] = cvt_h2(__ldg(Wk + (k0 + 8) * 32 + nn),
                                   __ldg(Wk + (k0 + 9) * 32 + nn));
        }
    }
}

// ---------------------------------------------------------------------------
// build_rb, one 256-voxel unit (nsh aliased onto dynamic smem)
// ---------------------------------------------------------------------------
__device__ void build_rb_unit(int* nsh, const int* __restrict__ nbr, int n, int unit)
{
    const int tid  = threadIdx.x;
    const int lane = tid & 31;
    const long long base = (long long)unit * 256;

    for (int i = tid; i < 256 * 27; i += 256) {
        long long g = base * 27 + i;
        nsh[i] = (g < (long long)n * 27) ? nbr[g] : n;
    }
    __syncthreads();

    const int v = (int)(base + tid);
    const bool live = v < n;

    #pragma unroll 1
    for (int j = 0; j < NBK; ++j) {
        int k = (j < 13) ? j : j + 1;
        int u = nsh[tid * 27 + k];
        bool want = live && ((unsigned)u < (unsigned)n);
        unsigned m = __ballot_sync(0xffffffffu, want);
        int rank = __popc(m & ((1u << lane) - 1));
        int leader = (m != 0u) ? (__ffs(m) - 1) : 0;
        int bp = 0;
        if (m != 0u && lane == leader) bp = atomicAdd(&g_kcnt[j], __popc(m));
        bp = __shfl_sync(0xffffffffu, bp, leader);
        int pos = bp + rank;
        if (want && pos < SEG) g_rb[j * SEG + pos] = make_int2(v, u);
    }
    __syncthreads();
}

// ---------------------------------------------------------------------------
// FMA pair GEMM + nb unit (256 entries of one tap segment)
// ---------------------------------------------------------------------------
__device__ __forceinline__ void pair_gemm(const u64* f, const u64* wsp, int p,
                                          float& rA, float& rB)
{
    const ulonglong2* row = (const ulonglong2*)(f + p * 32);
    u64 aE = 0ull, aO = 0ull;
    #pragma unroll
    for (int c2 = 0; c2 < 16; ++c2) {
        ulonglong2 q = row[c2];
        fma2(aE, q.x, wsp[2 * c2]);
        fma2(aO, q.y, wsp[2 * c2 + 1]);
    }
    float2 e = unpack2(aE), o = unpack2(aO);
    rA = e.x + o.x;
    rB = e.y + o.y;
}

__device__ void nb_unit(char* dyn, const __half* __restrict__ x,
                        const float* __restrict__ W, int kstride, int hoff,
                        __half* __restrict__ acc, int n, int u)
{
    const int j   = u / BLKSEG;
    const int bis = u % BLKSEG;
    const int cnt = g_kcnt[j];
    if (bis * 256 >= cnt) return;   // block-uniform

    const int k = (j < 13) ? j : j + 1;
    const float* Wk = W + (size_t)k * kstride + hoff;

    const int lane = threadIdx.x & 31;
    const int warp = threadIdx.x >> 5;

    u64 wsp[32];
    #pragma unroll
    for (int c = 0; c < 32; ++c) wsp[c] = splat2(__ldg(Wk + c * 32 + lane));

    const int eidx = bis * 256 + warp * 32 + lane;
    int2 e = (eidx < cnt) ? __ldg(&g_rb[j * SEG + eidx]) : make_int2(n, 0);

    u64* f = (u64*)dyn + warp * 512;
    #pragma unroll 4
    for (int p = 0; p < 16; ++p) {
        int uA = __shfl_sync(0xffffffffu, e.y, 2 * p);
        int uB = __shfl_sync(0xffffffffu, e.y, 2 * p + 1);
        f[p * 32 + lane] = pack2(__half2float(__ldg(x + (size_t)uA * 32 + lane)),
                                 __half2float(__ldg(x + (size_t)uB * 32 + lane)));
    }
    __syncwarp();

    #pragma unroll 2
    for (int p = 0; p < 16; ++p) {
        float rA, rB;
        pair_gemm(f, wsp, p, rA, rB);
        int vA = __shfl_sync(0xffffffffu, e.x, 2 * p);
        int vB = __shfl_sync(0xffffffffu, e.x, 2 * p + 1);
        float pA = __shfl_xor_sync(0xffffffffu, rA, 1);
        float pB = __shfl_xor_sync(0xffffffffu, rB, 1);
        unsigned hv;
        int v;
        if ((lane & 1) == 0) { hv = cvt_h2(rA, pA); v = vA; }
        else                 { hv = cvt_h2(pB, rB); v = vB; }
        redadd_h2(acc + (size_t)v * 32 + (lane & ~1), hv);
    }
    __syncwarp();
}

// ---------------------------------------------------------------------------
// epi phase: HMMA center tap -> smem transpose -> lane=voxel coalesced IO
// ---------------------------------------------------------------------------
template <int MODE, typename TOUT>
__device__ void epi_phase(char* dyn, float* ssm, float* bsm,
                          const __half* __restrict__ acc,
                          const float* __restrict__ bnp,
                          const __half* __restrict__ x0, const float* __restrict__ Wc0,
                          const __half* __restrict__ x1, const float* __restrict__ Wc1,
                          const __half* __restrict__ res,
                          TOUT* __restrict__ out, int n, int nblk)
{
    const int tid  = threadIdx.x;
    const int lane = tid & 31;
    const int warp = tid >> 5;
    const int gq = lane >> 2, t = lane & 3;

    if (tid < 32) {
        float s = __ldg(bnp + tid) * rsqrtf(__ldg(bnp + 96 + tid) + 1e-3f);
        ssm[tid] = s;
        bsm[tid] = __ldg(bnp + 32 + tid) - __ldg(bnp + 64 + tid) * s;
    }
    __syncthreads();

    char* x0b = dyn + warp * WSPAN;
    char* dsm = x0b + 32 * ROWB;
    char* x1b = dsm + 32 * ROWB;

    unsigned bf0[4][2][2];
    buildB(bf0, Wc0, lane);
    unsigned bf1[4][2][2];
    if (MODE == 2) buildB(bf1, Wc1, lane);

    const int ntiles = (n + 31) / 32;
    for (int tile = blockIdx.x * 8 + warp; tile < ntiles; tile += nblk * 8) {
        const int base = tile * 32;
        {
            int vox = base + lane;
            int uu = (vox < n) ? vox : 0;
            stage_row(x0b, lane, x0 + (size_t)uu * 32);
            if (MODE == 2) stage_row(x1b, lane, x1 + (size_t)uu * 32);
        }
        __syncwarp();

        #pragma unroll
        for (int mt = 0; mt < 2; ++mt) {
            unsigned a0[2][4];
            ldmA(a0[0], x0b, mt, 0, lane);
            ldmA(a0[1], x0b, mt, 1, lane);
            float d[4][4] = {};
            #pragma unroll
            for (int nb = 0; nb < 4; ++nb) {
                mma16816(d[nb], a0[0], bf0[nb][0]);
                mma16816(d[nb], a0[1], bf0[nb][1]);
            }
            if (MODE == 2) {
                unsigned a1[2][4];
                ldmA(a1[0], x1b, mt, 0, lane);
                ldmA(a1[1], x1b, mt, 1, lane);
                #pragma unroll
                for (int nb = 0; nb < 4; ++nb) {
                    mma16816(d[nb], a1[0], bf1[nb][0]);
                    mma16816(d[nb], a1[1], bf1[nb][1]);
                }
            }
            #pragma unroll
            for (int rw = 0; rw < 2; ++rw) {
                int r  = mt * 16 + 8 * rw + gq;
                int sw = (r >> 3) & 3;
                char* rb = dsm + r * ROWB;
                #pragma unroll
                for (int nb = 0; nb < 4; ++nb)
                    *(unsigned*)(rb + ((nb ^ sw) << 4) + 4 * t) =
                        cvt_h2(d[nb][2 * rw], d[nb][2 * rw + 1]);
            }
        }
        __syncwarp();

        // lane = voxel coalesced epilogue
        const int v = base + lane;
        if (v < n) {
            const int sw = (lane >> 3) & 3;
            const char* drb = dsm + lane * ROWB;
            const char* x0r = x0b + lane * ROWB;
            const char* x1r = x1b + lane * ROWB;

            #pragma unroll
            for (int hf = 0; hf < 2; ++hf) {
                uint4 db0 = *(const uint4*)(drb + (((2 * hf)     ^ sw) << 4));
                uint4 db1 = *(const uint4*)(drb + (((2 * hf + 1) ^ sw) << 4));
                uint4 ab0 = __ldg((const uint4*)(acc + (size_t)v * 32 + 16 * hf));
                uint4 ab1 = __ldg((const uint4*)(acc + (size_t)v * 32 + 16 * hf + 8));
                unsigned dbits[8] = {db0.x, db0.y, db0.z, db0.w,
                                     db1.x, db1.y, db1.z, db1.w};
                unsigned abits[8] = {ab0.x, ab0.y, ab0.z, ab0.w,
                                     ab1.x, ab1.y, ab1.z, ab1.w};
                unsigned rbits[8];
                if (MODE == 1) {
                    uint4 rb0 = __ldg((const uint4*)(res + (size_t)v * 32 + 16 * hf));
                    uint4 rb1 = __ldg((const uint4*)(res + (size_t)v * 32 + 16 * hf + 8));
                    rbits[0] = rb0.x; rbits[1] = rb0.y; rbits[2] = rb0.z; rbits[3] = rb0.w;
                    rbits[4] = rb1.x; rbits[5] = rb1.y; rbits[6] = rb1.z; rbits[7] = rb1.w;
                }
                unsigned xbits[16];
                if (MODE == 2) {
                    const char* xr = hf ? x1r : x0r;
                    #pragma unroll
                    for (int c = 0; c < 4; ++c) {
                        uint4 q = *(const uint4*)(xr + ((c ^ sw) << 4));
                        xbits[4 * c] = q.x; xbits[4 * c + 1] = q.y;
                        xbits[4 * c + 2] = q.z; xbits[4 * c + 3] = q.w;
                    }
                }

                float y[16];
                #pragma unroll
                for (int i = 0; i < 8; ++i) {
                    float2 dv = h2f(dbits[i]);
                    float2 av = h2f(abits[i]);
                    float2 sv = ((const float2*)ssm)[8 * hf + i];
                    float2 bv = ((const float2*)bsm)[8 * hf + i];
                    float y0 = (av.x + dv.x) * sv.x + bv.x;
                    float y1 = (av.y + dv.y) * sv.y + bv.y;
                    if (MODE == 1) {
                        float2 rv = h2f(rbits[i]);
                        y0 += rv.x; y1 += rv.y;
                    }
                    y0 = fmaxf(y0, 0.0f);
                    y1 = fmaxf(y1, 0.0f);
                    if (MODE == 2) {
                        float2 q0 = h2f(xbits[2 * i]);
                        float2 q1 = h2f(xbits[2 * i + 1]);
                        y0 += q0.x + q0.y;
                        y1 += q1.x + q1.y;
                    }
                    y[2 * i] = y0;
                    y[2 * i + 1] = y1;
                }

                if (sizeof(TOUT) == 2) {
                    uint4 o0;
                    o0.x = cvt_h2(y[0], y[1]);   o0.y = cvt_h2(y[2], y[3]);
                    o0.z = cvt_h2(y[4], y[5]);   o0.w = cvt_h2(y[6], y[7]);
                    uint4 o1;
                    o1.x = cvt_h2(y[8], y[9]);   o1.y = cvt_h2(y[10], y[11]);
                    o1.z = cvt_h2(y[12], y[13]); o1.w = cvt_h2(y[14], y[15]);
                    *(uint4*)((__half*)out + (size_t)v * 32 + 16 * hf)     = o0;
                    *(uint4*)((__half*)out + (size_t)v * 32 + 16 * hf + 8) = o1;
                } else {
                    float* op = (float*)out + (size_t)v * 32 + 16 * hf;
                    #pragma unroll
                    for (int q = 0; q < 4; ++q)
                        *(float4*)(op + 4 * q) =
                            make_float4(y[4 * q], y[4 * q + 1],
                                        y[4 * q + 2], y[4 * q + 3]);
                }
            }
        }
        __syncwarp();
    }
}

// ---------------------------------------------------------------------------
// the persistent mega-kernel
// ---------------------------------------------------------------------------
__global__ __launch_bounds__(256, 3)
void mega(const float* __restrict__ lat, const float* __restrict__ bot,
          const float* __restrict__ Wt1, const float* __restrict__ bnt1,
          const float* __restrict__ Wt2, const float* __restrict__ bnt2,
          const float* __restrict__ Wm,  const float* __restrict__ bnm,
          const float* __restrict__ Wi,  const float* __restrict__ bni,
          const int* __restrict__ nbr, float* __restrict__ out,
          int n, int nblk)
{
    extern __shared__ __align__(16) char dyn[];
    __shared__ float ssm[32], bsm[32];

    __half* a1 = g_acc;
    __half* a2 = g_acc + 1 * ASTRIDE;
    __half* a3 = g_acc + 2 * ASTRIDE;
    __half* a4 = g_acc + 3 * ASTRIDE;

    const size_t gtid = (size_t)blockIdx.x * 256 + threadIdx.x;
    const size_t gstr = (size_t)nblk * 256;

    // ---- P0: zero acc + kcnt, convert lat/bot to fp16 ----
    if (blockIdx.x == 0 && threadIdx.x < 32) g_kcnt[threadIdx.x] = 0;
    {
        const size_t tot = (4 * ASTRIDE) / 8;    // uint4 units
        for (size_t i = gtid; i < tot; i += gstr)
            ((uint4*)g_acc)[i] = make_uint4(0, 0, 0, 0);

        const size_t cnt8 = (size_t)n * 4;       // 8-float units
        for (size_t i = gtid; i < cnt8; i += gstr) {
            float4 a = __ldg((const float4*)(lat + i * 8));
            float4 b = __ldg((const float4*)(lat + i * 8 + 4));
            uint4 v;
            v.x = cvt_h2(a.x, a.y); v.y = cvt_h2(a.z, a.w);
            v.z = cvt_h2(b.x, b.y); v.w = cvt_h2(b.z, b.w);
            ((uint4*)g_hlat)[i] = v;
        }
        for (size_t i = gtid; i < cnt8; i += gstr) {
            float4 a = __ldg((const float4*)(bot + i * 8));
            float4 b = __ldg((const float4*)(bot + i * 8 + 4));
            uint4 v;
            v.x = cvt_h2(a.x, a.y); v.y = cvt_h2(a.z, a.w);
            v.z = cvt_h2(b.x, b.y); v.w = cvt_h2(b.z, b.w);
            ((uint4*)g_hbot)[i] = v;
        }
    }
    gridbar(nblk);

    // ---- P1: build rulebook ----
    {
        const int nunits = (n + 255) / 256;
        for (int u = blockIdx.x; u < nunits; u += nblk)
            build_rb_unit((int*)dyn, nbr, n, u);
    }
    gridbar(nblk);

    // ---- P2: nb(lat -> a1) + nb(bot, Wm h0 -> a3) ----
    {
        const int NU = NBK * BLKSEG;
        for (int u = blockIdx.x; u < 2 * NU; u += nblk) {
            if (u < NU) nb_unit(dyn, g_hlat, Wt1, 1024, 0, a1, n, u);
            else        nb_unit(dyn, g_hbot, Wm, 2048, 0, a3, n, u - NU);
        }
    }
    gridbar(nblk);

    // ---- P3: epi1 -> h1 ----
    epi_phase<0, __half>(dyn, ssm, bsm, a1, bnt1, g_hlat, Wt1 + 13 * 1024,
                         nullptr, nullptr, nullptr, g_h1, n, nblk);
    gridbar(nblk);

    // ---- P4: nb(h1 -> a2) ----
    for (int u = blockIdx.x; u < NBK * BLKSEG; u += nblk)
        nb_unit(dyn, g_h1, Wt2, 1024, 0, a2, n, u);
    gridbar(nblk);

    // ---- P5: epi2 (+res hlat) -> h2 ----
    epi_phase<1, __half>(dyn, ssm, bsm, a2, bnt2, g_h1, Wt2 + 13 * 1024,
                         nullptr, nullptr, g_hlat, g_h2, n, nblk);
    gridbar(nblk);

    // ---- P6: nb(h2, Wm h1 -> a3) ----
    for (int u = blockIdx.x; u < NBK * BLKSEG; u += nblk)
        nb_unit(dyn, g_h2, Wm, 2048, 1024, a3, n, u);
    gridbar(nblk);

    // ---- P7: epi3 (2-half center + xred) -> h3 ----
    epi_phase<2, __half>(dyn, ssm, bsm, a3, bnm, g_hbot, Wm + 13 * 2048,
                         g_h2, Wm + 13 * 2048 + 1024, nullptr, g_h3, n, nblk);
    gridbar(nblk);

    // ---- P8: nb(h3 -> a4) ----
    for (int u = blockIdx.x; u < NBK * BLKSEG; u += nblk)
        nb_unit(dyn, g_h3, Wi, 1024, 0, a4, n, u);
    gridbar(nblk);

    // ---- P9: epi4 -> out (fp32) ----
    epi_phase<0, float>(dyn, ssm, bsm, a4, bni, g_h3, Wi + 13 * 1024,
                        nullptr, nullptr, nullptr, out, n, nblk);
}

// ---------------------------------------------------------------------------
extern "C" void kernel_launch(void* const* d_in, const int* in_sizes, int n_in,
                              void* d_out, int out_size)
{
    const float* lat  = (const float*)d_in[0];
    const float* bot  = (const float*)d_in[1];
    const float* Wt1  = (const float*)d_in[2];
    const float* bnt1 = (const float*)d_in[3];
    const float* Wt2  = (const float*)d_in[4];
    const float* bnt2 = (const float*)d_in[5];
    const float* Wm   = (const float*)d_in[6];
    const float* bnm  = (const float*)d_in[7];
    const float* Wi   = (const float*)d_in[8];
    const float* bni  = (const float*)d_in[9];
    const int*   nbr  = (const int*)d_in[10];

    const int n = in_sizes[0] / NC;

    static int nblk = 0;
    if (nblk == 0) {
        cudaFuncSetAttribute(mega, cudaFuncAttributeMaxDynamicSharedMemorySize,
                             DYNSM);
        int B = 0, sm = 0, dev = 0;
        cudaGetDevice(&dev);
        cudaDeviceGetAttribute(&sm, cudaDevAttrMultiProcessorCount, dev);
        cudaOccupancyMaxActiveBlocksPerMultiprocessor(&B, mega, 256, DYNSM);
        if (B < 1) B = 1;
        nblk = B * sm;
    }

    mega<<<nblk, 256, DYNSM>>>(lat, bot, Wt1, bnt1, Wt2, bnt2, Wm, bnm,
                               Wi, bni, nbr, (float*)d_out, n, nblk);
}

// round 13
// speedup vs baseline: 1.0006x; 1.0006x over previous
#include <cuda_runtime.h>
#include <cuda_fp16.h>

// ---------------------------------------------------------------------------
// UNetV2 on GB300 (R13 = R10 structure + transposed epilogue):
//  - nb_conv: FMA f32x2 gather-GEMM, shuffle-staged coalesced gathers,
//    lane=cout, coalesced fp16x2 atomics
//  - epi: HMMA center tap -> smem transpose -> lane=voxel coalesced IO
//  - per-slice memsets + bot-half nb conv forked onto side streams
// ---------------------------------------------------------------------------

#define MAXN 500000
#define NC   32
#define SEG  16384
#define NBK  26
#define BLKSEG 64
#define ASTRIDE ((size_t)(MAXN + 1) * NC)
#define ACCBYTES (ASTRIDE * sizeof(__half))
#define ROWB 80
#define WSPAN (3 * 32 * ROWB)
#define EPIDYN (8 * WSPAN)             // 61440 B dynamic smem for epi

static __device__ __half g_acc[4 * ASTRIDE];
static __device__ __half g_h1[MAXN * NC];
static __device__ __half g_h2[MAXN * NC];
static __device__ __half g_h3[MAXN * NC];
static __device__ int2   g_rb[NBK * SEG];
static __device__ int    g_kcnt[32];

typedef unsigned long long u64;

__device__ __forceinline__ u64 splat2(float a) {
    u64 r; asm("mov.b64 %0, {%1, %1};" : "=l"(r) : "f"(a)); return r;
}
__device__ __forceinline__ u64 pack2(float a, float b) {
    u64 r; asm("mov.b64 %0, {%1, %2};" : "=l"(r) : "f"(a), "f"(b)); return r;
}
__device__ __forceinline__ void fma2(u64& d, u64 a, u64 b) {
    asm("fma.rn.f32x2 %0, %1, %2, %3;" : "=l"(d) : "l"(a), "l"(b), "l"(d));
}
__device__ __forceinline__ float2 unpack2(u64 a) {
    float2 r; asm("mov.b64 {%0, %1}, %2;" : "=f"(r.x), "=f"(r.y) : "l"(a)); return r;
}
__device__ __forceinline__ unsigned cvt_h2(float lo, float hi) {
    unsigned r;
    asm("cvt.rn.f16x2.f32 %0, %1, %2;" : "=r"(r) : "f"(hi), "f"(lo));
    return r;
}
__device__ __forceinline__ float2 h2f(unsigned u) {
    return __half22float2(*(__half2*)&u);
}
__device__ __forceinline__ void redadd_h2(__half* p, unsigned hv) {
    asm volatile("red.global.add.noftz.f16x2 [%0], %1;" :: "l"(p), "r"(hv) : "memory");
}
__device__ __forceinline__ float loadf(const float* p)  { return __ldg(p); }
__device__ __forceinline__ float loadf(const __half* p) { return __half2float(__ldg(p)); }

// ---------------------------------------------------------------------------
// HMMA helpers
// ---------------------------------------------------------------------------
__device__ __forceinline__ void stage_row(char* wbase, int r, const __half* row) {
    const uint4* s = (const uint4*)row;
    int sw = (r >> 3) & 3;
    char* rb = wbase + r * ROWB;
    #pragma unroll
    for (int c = 0; c < 4; ++c)
        *(uint4*)(rb + ((c ^ sw) << 4)) = __ldg(s + c);
}
__device__ __forceinline__ void stage_row(char* wbase, int r, const float* row) {
    const float4* s = (const float4*)row;
    int sw = (r >> 3) & 3;
    char* rb = wbase + r * ROWB;
    #pragma unroll
    for (int c = 0; c < 4; ++c) {
        float4 f0 = __ldg(s + 2 * c);
        float4 f1 = __ldg(s + 2 * c + 1);
        uint4 v;
        v.x = cvt_h2(f0.x, f0.y); v.y = cvt_h2(f0.z, f0.w);
        v.z = cvt_h2(f1.x, f1.y); v.w = cvt_h2(f1.z, f1.w);
        *(uint4*)(rb + ((c ^ sw) << 4)) = v;
    }
}
__device__ __forceinline__ void ldmA(unsigned a[4], const char* wbase, int mt,
                                     int kb, int lane) {
    int r  = mt * 16 + (lane & 15);
    int lc = 2 * kb + (lane >> 4);
    unsigned addr = (unsigned)__cvta_generic_to_shared(
        wbase + r * ROWB + ((lc ^ ((r >> 3) & 3)) << 4));
    asm volatile("ldmatrix.sync.aligned.m8n8.x4.shared.b16 {%0,%1,%2,%3}, [%4];"
                 : "=r"(a[0]), "=r"(a[1]), "=r"(a[2]), "=r"(a[3]) : "r"(addr));
}
__device__ __forceinline__ void mma16816(float d[4], const unsigned a[4],
                                         const unsigned b[2]) {
    asm volatile(
        "mma.sync.aligned.m16n8k16.row.col.f32.f16.f16.f32 "
        "{%0,%1,%2,%3},{%4,%5,%6,%7},{%8,%9},{%0,%1,%2,%3};"
        : "+f"(d[0]), "+f"(d[1]), "+f"(d[2]), "+f"(d[3])
        : "r"(a[0]), "r"(a[1]), "r"(a[2]), "r"(a[3]), "r"(b[0]), "r"(b[1]));
}
__device__ __forceinline__ void buildB(unsigned bf[4][2][2], const float* Wk,
                                       int lane) {
    int g = lane >> 2, t = lane & 3;
    #pragma unroll
    for (int nb = 0; nb < 4; ++nb) {
        int nn = nb * 8 + g;
        #pragma unroll
        for (int kb = 0; kb < 2; ++kb) {
            int k0 = 16 * kb + 2 * t;
            bf[nb][kb][0] = cvt_h2(__ldg(Wk + k0 * 32 + nn),
                                   __ldg(Wk + (k0 + 1) * 32 + nn));
            bf[nb][kb][1] = cvt_h2(__ldg(Wk + (k0 + 8) * 32 + nn),
                                   __ldg(Wk + (k0 + 9) * 32 + nn));
        }
    }
}

// ---------------------------------------------------------------------------
__global__ __launch_bounds__(256)
void build_rb(const int* __restrict__ nbr, int n)
{
    __shared__ int nsh[256 * 27];
    const int tid  = threadIdx.x;
    const int lane = tid & 31;
    const long long base = (long long)blockIdx.x * 256;

    for (int i = tid; i < 256 * 27; i += 256) {
        long long g = base * 27 + i;
        nsh[i] = (g < (long long)n * 27) ? nbr[g] : n;
    }
    __syncthreads();

    const int v = (int)(base + tid);
    const bool live = v < n;

    #pragma unroll 1
    for (int j = 0; j < NBK; ++j) {
        int k = (j < 13) ? j : j + 1;
        int u = nsh[tid * 27 + k];
        bool want = live && ((unsigned)u < (unsigned)n);
        unsigned m = __ballot_sync(0xffffffffu, want);
        int rank = __popc(m & ((1u << lane) - 1));
        int leader = (m != 0u) ? (__ffs(m) - 1) : 0;
        int bp = 0;
        if (m != 0u && lane == leader) bp = atomicAdd(&g_kcnt[j], __popc(m));
        bp = __shfl_sync(0xffffffffu, bp, leader);
        int pos = bp + rank;
        if (want && pos < SEG) g_rb[j * SEG + pos] = make_int2(v, u);
    }
}

// ---------------------------------------------------------------------------
// FMA pair GEMM (nb_conv)
// ---------------------------------------------------------------------------
__device__ __forceinline__ void pair_gemm(const u64* f, const u64* wsp, int p,
                                          float& rA, float& rB)
{
    const ulonglong2* row = (const ulonglong2*)(f + p * 32);
    u64 aE = 0ull, aO = 0ull;
    #pragma unroll
    for (int c2 = 0; c2 < 16; ++c2) {
        ulonglong2 q = row[c2];
        fma2(aE, q.x, wsp[2 * c2]);
        fma2(aO, q.y, wsp[2 * c2 + 1]);
    }
    float2 e = unpack2(aE), o = unpack2(aO);
    rA = e.x + o.x;
    rB = e.y + o.y;
}

// ---------------------------------------------------------------------------
// neighbor taps: FMA pipeline, coalesced fp16x2 atomics (R10 form)
// ---------------------------------------------------------------------------
template <typename T>
__global__ __launch_bounds__(256)
void nb_conv(const T* __restrict__ x, const float* __restrict__ W,
             int kstride, int hoff, __half* __restrict__ acc, int n)
{
    __shared__ u64 ft[8 * 512];
    const int j   = blockIdx.x / BLKSEG;
    const int bis = blockIdx.x % BLKSEG;
    const int cnt = g_kcnt[j];
    if (bis * 256 >= cnt) return;

    const int k = (j < 13) ? j : j + 1;
    const float* Wk = W + (size_t)k * kstride + hoff;

    const int lane = threadIdx.x & 31;
    const int warp = threadIdx.x >> 5;

    u64 wsp[32];
    #pragma unroll
    for (int c = 0; c < 32; ++c) wsp[c] = splat2(__ldg(Wk + c * 32 + lane));

    const int eidx = bis * 256 + warp * 32 + lane;
    int2 e = (eidx < cnt) ? __ldg(&g_rb[j * SEG + eidx]) : make_int2(n, 0);

    u64* f = ft + warp * 512;
    #pragma unroll 4
    for (int p = 0; p < 16; ++p) {
        int uA = __shfl_sync(0xffffffffu, e.y, 2 * p);
        int uB = __shfl_sync(0xffffffffu, e.y, 2 * p + 1);
        f[p * 32 + lane] = pack2(loadf(x + (size_t)uA * 32 + lane),
                                 loadf(x + (size_t)uB * 32 + lane));
    }
    __syncwarp();

    #pragma unroll 2
    for (int p = 0; p < 16; ++p) {
        float rA, rB;
        pair_gemm(f, wsp, p, rA, rB);
        int vA = __shfl_sync(0xffffffffu, e.x, 2 * p);
        int vB = __shfl_sync(0xffffffffu, e.x, 2 * p + 1);
        float pA = __shfl_xor_sync(0xffffffffu, rA, 1);
        float pB = __shfl_xor_sync(0xffffffffu, rB, 1);
        unsigned hv;
        int v;
        if ((lane & 1) == 0) { hv = cvt_h2(rA, pA); v = vA; }
        else                 { hv = cvt_h2(pB, rB); v = vB; }
        redadd_h2(acc + (size_t)v * 32 + (lane & ~1), hv);
    }
}

// ---------------------------------------------------------------------------
// epilogue: HMMA center tap -> smem transpose -> lane=voxel coalesced IO
//  MODE 0: y = relu(bn(acc + Wc0^T x0))
//  MODE 1: y = relu(bn(acc + Wc0^T x0) + res)         (res fp32)
//  MODE 2: y = relu(bn(acc + Wc0^T x0 + Wc1^T x1)) + xred(cat(x0,x1)) [smem]
// ---------------------------------------------------------------------------
template <int MODE, typename T0, typename TOUT>
__global__ __launch_bounds__(256)
void epi(const __half* __restrict__ acc, const float* __restrict__ bnp,
         const T0* __restrict__ x0, const float* __restrict__ Wc0,
         const __half* __restrict__ x1, const float* __restrict__ Wc1,
         const float* __restrict__ res,
         TOUT* __restrict__ out, int n)
{
    extern __shared__ __align__(16) char xsm[];
    __shared__ float ssm[32], bsm[32];

    const int tid  = threadIdx.x;
    const int lane = tid & 31;
    const int warp = tid >> 5;
    const int gq = lane >> 2, t = lane & 3;

    if (tid < 32) {
        float s = __ldg(bnp + tid) * rsqrtf(__ldg(bnp + 96 + tid) + 1e-3f);
        ssm[tid] = s;
        bsm[tid] = __ldg(bnp + 32 + tid) - __ldg(bnp + 64 + tid) * s;
    }
    __syncthreads();

    const int base = (blockIdx.x * 8 + warp) * 32;
    if (base >= n) return;

    char* x0b = xsm + warp * WSPAN;
    char* dsm = x0b + 32 * ROWB;
    char* x1b = dsm + 32 * ROWB;

    {
        int vox = base + lane;
        int uu = (vox < n) ? vox : 0;
        stage_row(x0b, lane, x0 + (size_t)uu * 32);
        if (MODE == 2) stage_row(x1b, lane, x1 + (size_t)uu * 32);
    }
    __syncwarp();

    unsigned bf0[4][2][2];
    buildB(bf0, Wc0, lane);
    unsigned bf1[4][2][2];
    if (MODE == 2) buildB(bf1, Wc1, lane);

    #pragma unroll
    for (int mt = 0; mt < 2; ++mt) {
        unsigned a0[2][4];
        ldmA(a0[0], x0b, mt, 0, lane);
        ldmA(a0[1], x0b, mt, 1, lane);
        float d[4][4] = {};
        #pragma unroll
        for (int nb = 0; nb < 4; ++nb) {
            mma16816(d[nb], a0[0], bf0[nb][0]);
            mma16816(d[nb], a0[1], bf0[nb][1]);
        }
        if (MODE == 2) {
            unsigned a1[2][4];
            ldmA(a1[0], x1b, mt, 0, lane);
            ldmA(a1[1], x1b, mt, 1, lane);
            #pragma unroll
            for (int nb = 0; nb < 4; ++nb) {
                mma16816(d[nb], a1[0], bf1[nb][0]);
                mma16816(d[nb], a1[1], bf1[nb][1]);
            }
        }
        // spill D fragments to dsm (fp16, swizzled)
        #pragma unroll
        for (int rw = 0; rw < 2; ++rw) {
            int r  = mt * 16 + 8 * rw + gq;
            int sw = (r >> 3) & 3;
            char* rb = dsm + r * ROWB;
            #pragma unroll
            for (int nb = 0; nb < 4; ++nb)
                *(unsigned*)(rb + ((nb ^ sw) << 4) + 4 * t) =
                    cvt_h2(d[nb][2 * rw], d[nb][2 * rw + 1]);
        }
    }
    __syncwarp();

    // ---- lane = voxel coalesced epilogue ----
    const int v = base + lane;
    if (v >= n) return;

    const int sw = (lane >> 3) & 3;
    const char* drb = dsm + lane * ROWB;
    const char* x0r = x0b + lane * ROWB;
    const char* x1r = x1b + lane * ROWB;

    #pragma unroll
    for (int hf = 0; hf < 2; ++hf) {
        uint4 db0 = *(const uint4*)(drb + (((2 * hf)     ^ sw) << 4));
        uint4 db1 = *(const uint4*)(drb + (((2 * hf + 1) ^ sw) << 4));
        uint4 ab0 = __ldg((const uint4*)(acc + (size_t)v * 32 + 16 * hf));
        uint4 ab1 = __ldg((const uint4*)(acc + (size_t)v * 32 + 16 * hf + 8));
        unsigned dbits[8] = {db0.x, db0.y, db0.z, db0.w, db1.x, db1.y, db1.z, db1.w};
        unsigned abits[8] = {ab0.x, ab0.y, ab0.z, ab0.w, ab1.x, ab1.y, ab1.z, ab1.w};
        float rvals[16];
        if (MODE == 1) {
            const float* rp = res + (size_t)v * 32 + 16 * hf;
            #pragma unroll
            for (int q = 0; q < 4; ++q) {
                float4 rq = __ldg((const float4*)(rp + 4 * q));
                rvals[4 * q] = rq.x; rvals[4 * q + 1] = rq.y;
                rvals[4 * q + 2] = rq.z; rvals[4 * q + 3] = rq.w;
            }
        }
        unsigned xbits[16];
        if (MODE == 2) {
            const char* xr = hf ? x1r : x0r;
            #pragma unroll
            for (int c = 0; c < 4; ++c) {
                uint4 q = *(const uint4*)(xr + ((c ^ sw) << 4));
                xbits[4 * c] = q.x; xbits[4 * c + 1] = q.y;
                xbits[4 * c + 2] = q.z; xbits[4 * c + 3] = q.w;
            }
        }

        float y[16];
        #pragma unroll
        for (int i = 0; i < 8; ++i) {
            float2 dv = h2f(dbits[i]);
            float2 av = h2f(abits[i]);
            float2 sv = ((const float2*)ssm)[8 * hf + i];
            float2 bv = ((const float2*)bsm)[8 * hf + i];
            float y0 = (av.x + dv.x) * sv.x + bv.x;
            float y1 = (av.y + dv.y) * sv.y + bv.y;
            if (MODE == 1) {
                y0 += rvals[2 * i];
                y1 += rvals[2 * i + 1];
            }
            y0 = fmaxf(y0, 0.0f);
            y1 = fmaxf(y1, 0.0f);
            if (MODE == 2) {
                float2 q0 = h2f(xbits[2 * i]);
                float2 q1 = h2f(xbits[2 * i + 1]);
                y0 += q0.x + q0.y;
                y1 += q1.x + q1.y;
            }
            y[2 * i] = y0;
            y[2 * i + 1] = y1;
        }

        if (sizeof(TOUT) == 2) {
            uint4 o0, o1;
            o0.x = cvt_h2(y[0], y[1]);   o0.y = cvt_h2(y[2], y[3]);
            o0.z = cvt_h2(y[4], y[5]);   o0.w = cvt_h2(y[6], y[7]);
            o1.x = cvt_h2(y[8], y[9]);   o1.y = cvt_h2(y[10], y[11]);
            o1.z = cvt_h2(y[12], y[13]); o1.w = cvt_h2(y[14], y[15]);
            *(uint4*)((__half*)out + (size_t)v * 32 + 16 * hf)     = o0;
            *(uint4*)((__half*)out + (size_t)v * 32 + 16 * hf + 8) = o1;
        } else {
            float* op = (float*)out + (size_t)v * 32 + 16 * hf;
            #pragma unroll
            for (int q = 0; q < 4; ++q)
                *(float4*)(op + 4 * q) = make_float4(y[4 * q], y[4 * q + 1],
                                                     y[4 * q + 2], y[4 * q + 3]);
        }
    }
}

// ---------------------------------------------------------------------------
extern "C" void kernel_launch(void* const* d_in, const int* in_sizes, int n_in,
                              void* d_out, int out_size)
{
    const float* lat  = (const float*)d_in[0];
    const float* bot  = (const float*)d_in[1];
    const float* Wt1  = (const float*)d_in[2];
    const float* bnt1 = (const float*)d_in[3];
    const float* Wt2  = (const float*)d_in[4];
    const float* bnt2 = (const float*)d_in[5];
    const float* Wm   = (const float*)d_in[6];
    const float* bnm  = (const float*)d_in[7];
    const float* Wi   = (const float*)d_in[8];
    const float* bni  = (const float*)d_in[9];
    const int*   nbr  = (const int*)d_in[10];

    const int n = in_sizes[0] / NC;

    __half *accb, *h1, *h2, *h3;
    int* kcnt;
    cudaGetSymbolAddress((void**)&accb, g_acc);
    cudaGetSymbolAddress((void**)&h1, g_h1);
    cudaGetSymbolAddress((void**)&h2, g_h2);
    cudaGetSymbolAddress((void**)&h3, g_h3);
    cudaGetSymbolAddress((void**)&kcnt, g_kcnt);

    __half* a1 = accb;
    __half* a2 = accb + 1 * ASTRIDE;
    __half* a3 = accb + 2 * ASTRIDE;
    __half* a4 = accb + 3 * ASTRIDE;

    static cudaStream_t s1 = nullptr, s2 = nullptr;
    static cudaEvent_t e0 = nullptr, eB = nullptr, e2 = nullptr;
    static cudaEvent_t em1 = nullptr, em2 = nullptr, em3 = nullptr, em4 = nullptr;
    if (!s1) {
        cudaStreamCreateWithFlags(&s1, cudaStreamNonBlocking);
        cudaStreamCreateWithFlags(&s2, cudaStreamNonBlocking);
        cudaEventCreateWithFlags(&e0, cudaEventDisableTiming);
        cudaEventCreateWithFlags(&eB, cudaEventDisableTiming);
        cudaEventCreateWithFlags(&e2, cudaEventDisableTiming);
        cudaEventCreateWithFlags(&em1, cudaEventDisableTiming);
        cudaEventCreateWithFlags(&em2, cudaEventDisableTiming);
        cudaEventCreateWithFlags(&em3, cudaEventDisableTiming);
        cudaEventCreateWithFlags(&em4, cudaEventDisableTiming);
        cudaFuncSetAttribute(epi<0, float, __half>,
                             cudaFuncAttributeMaxDynamicSharedMemorySize, EPIDYN);
        cudaFuncSetAttribute(epi<1, __half, __half>,
                             cudaFuncAttributeMaxDynamicSharedMemorySize, EPIDYN);
        cudaFuncSetAttribute(epi<2, float, __half>,
                             cudaFuncAttributeMaxDynamicSharedMemorySize, EPIDYN);
        cudaFuncSetAttribute(epi<0, __half, float>,
                             cudaFuncAttributeMaxDynamicSharedMemorySize, EPIDYN);
    }

    const int gridC = (n + 255) / 256;
    const int gridN = NBK * BLKSEG;

    cudaMemsetAsync(kcnt, 0, 32 * sizeof(int), 0);
    cudaEventRecord(e0, 0);
    cudaStreamWaitEvent(s1, e0, 0);
    cudaMemsetAsync(a1, 0, ACCBYTES, s1); cudaEventRecord(em1, s1);
    cudaMemsetAsync(a3, 0, ACCBYTES, s1); cudaEventRecord(em3, s1);
    cudaMemsetAsync(a2, 0, ACCBYTES, s1); cudaEventRecord(em2, s1);
    cudaMemsetAsync(a4, 0, ACCBYTES, s1); cudaEventRecord(em4, s1);

    build_rb<<<gridC, 256>>>(nbr, n);
    cudaEventRecord(eB, 0);

    // fork: conv_m's bot-half neighbor pass overlaps conv1/conv2
    cudaStreamWaitEvent(s2, eB, 0);
    cudaStreamWaitEvent(s2, em3, 0);
    nb_conv<float><<<gridN, 256, 0, s2>>>(bot, Wm, 2048, 0, a3, n);
    cudaEventRecord(e2, s2);

    // conv1
    cudaStreamWaitEvent(0, em1, 0);
    nb_conv<float><<<gridN, 256>>>(lat, Wt1, 1024, 0, a1, n);
    epi<0, float, __half><<<gridC, 256, EPIDYN>>>(a1, bnt1, lat, Wt1 + 13 * 1024,
                                                  nullptr, nullptr, nullptr, h1, n);

    // conv2 (residual = lat fp32)
    cudaStreamWaitEvent(0, em2, 0);
    nb_conv<__half><<<gridN, 256>>>(h1, Wt2, 1024, 0, a2, n);
    epi<1, __half, __half><<<gridC, 256, EPIDYN>>>(a2, bnt2, h1, Wt2 + 13 * 1024,
                                                   nullptr, nullptr, lat, h2, n);

    // conv_m
    nb_conv<__half><<<gridN, 256>>>(h2, Wm, 2048, 1024, a3, n);
    cudaStreamWaitEvent(0, e2, 0);
    epi<2, float, __half><<<gridC, 256, EPIDYN>>>(a3, bnm, bot, Wm + 13 * 2048,
                                                  h2, Wm + 13 * 2048 + 1024,
                                                  nullptr, h3, n);

    // conv_inv
    cudaStreamWaitEvent(0, em4, 0);
    nb_conv<__half><<<gridN, 256>>>(h3, Wi, 1024, 0, a4, n);
    epi<0, __half, float><<<gridC, 256, EPIDYN>>>(a4, bni, h3, Wi + 13 * 1024,
                                                  nullptr, nullptr, nullptr,
                                                  (float*)d_out, n);
}

// round 14
// speedup vs baseline: 1.0946x; 1.0940x over previous
#include <cuda_runtime.h>
#include <cuda_fp16.h>

// ---------------------------------------------------------------------------
// UNetV2 on GB300 (R14 = R10 + sparsity-predicated acc reads):
//  - nb_conv: FMA f32x2 gather-GEMM, shuffle-staged coalesced gathers,
//    lane=cout, coalesced fp16x2 atomics
//  - epi: HMMA center tap, fragment-order IO, acc reads predicated on a
//    per-voxel has-neighbors flag (73% of rows are exactly zero -> skipped)
//  - per-slice memsets + bot-half nb conv forked onto side streams
// ---------------------------------------------------------------------------

#define MAXN 500000
#define NC   32
#define SEG  16384
#define NBK  26
#define BLKSEG 64
#define ASTRIDE ((size_t)(MAXN + 1) * NC)
#define ACCBYTES (ASTRIDE * sizeof(__half))
#define ROWB 80

static __device__ __half g_acc[4 * ASTRIDE];
static __device__ __half g_h1[MAXN * NC];
static __device__ __half g_h2[MAXN * NC];
static __device__ __half g_h3[MAXN * NC];
static __device__ int2   g_rb[NBK * SEG];
static __device__ int    g_kcnt[32];
static __device__ unsigned char g_flag[MAXN + 256];

typedef unsigned long long u64;

__device__ __forceinline__ u64 splat2(float a) {
    u64 r; asm("mov.b64 %0, {%1, %1};" : "=l"(r) : "f"(a)); return r;
}
__device__ __forceinline__ u64 pack2(float a, float b) {
    u64 r; asm("mov.b64 %0, {%1, %2};" : "=l"(r) : "f"(a), "f"(b)); return r;
}
__device__ __forceinline__ void fma2(u64& d, u64 a, u64 b) {
    asm("fma.rn.f32x2 %0, %1, %2, %3;" : "=l"(d) : "l"(a), "l"(b), "l"(d));
}
__device__ __forceinline__ float2 unpack2(u64 a) {
    float2 r; asm("mov.b64 {%0, %1}, %2;" : "=f"(r.x), "=f"(r.y) : "l"(a)); return r;
}
__device__ __forceinline__ unsigned cvt_h2(float lo, float hi) {
    unsigned r;
    asm("cvt.rn.f16x2.f32 %0, %1, %2;" : "=r"(r) : "f"(hi), "f"(lo));
    return r;
}
__device__ __forceinline__ float2 h2f(unsigned u) {
    return __half22float2(*(__half2*)&u);
}
__device__ __forceinline__ void redadd_h2(__half* p, unsigned hv) {
    asm volatile("red.global.add.noftz.f16x2 [%0], %1;" :: "l"(p), "r"(hv) : "memory");
}
__device__ __forceinline__ float loadf(const float* p)  { return __ldg(p); }
__device__ __forceinline__ float loadf(const __half* p) { return __half2float(__ldg(p)); }
__device__ __forceinline__ void storepair(float* p, float y0, float y1) {
    *(float2*)p = make_float2(y0, y1);
}
__device__ __forceinline__ void storepair(__half* p, float y0, float y1) {
    *(__half2*)p = __floats2half2_rn(y0, y1);
}

// ---------------------------------------------------------------------------
// HMMA helpers
// ---------------------------------------------------------------------------
__device__ __forceinline__ void stage_row(char* wbase, int r, const __half* row) {
    const uint4* s = (const uint4*)row;
    int sw = (r >> 3) & 3;
    char* rb = wbase + r * ROWB;
    #pragma unroll
    for (int c = 0; c < 4; ++c)
        *(uint4*)(rb + ((c ^ sw) << 4)) = __ldg(s + c);
}
__device__ __forceinline__ void stage_row(char* wbase, int r, const float* row) {
    const float4* s = (const float4*)row;
    int sw = (r >> 3) & 3;
    char* rb = wbase + r * ROWB;
    #pragma unroll
    for (int c = 0; c < 4; ++c) {
        float4 f0 = __ldg(s + 2 * c);
        float4 f1 = __ldg(s + 2 * c + 1);
        uint4 v;
        v.x = cvt_h2(f0.x, f0.y); v.y = cvt_h2(f0.z, f0.w);
        v.z = cvt_h2(f1.x, f1.y); v.w = cvt_h2(f1.z, f1.w);
        *(uint4*)(rb + ((c ^ sw) << 4)) = v;
    }
}
__device__ __forceinline__ void ldmA(unsigned a[4], const char* wbase, int mt,
                                     int kb, int lane) {
    int r  = mt * 16 + (lane & 15);
    int lc = 2 * kb + (lane >> 4);
    unsigned addr = (unsigned)__cvta_generic_to_shared(
        wbase + r * ROWB + ((lc ^ ((r >> 3) & 3)) << 4));
    asm volatile("ldmatrix.sync.aligned.m8n8.x4.shared.b16 {%0,%1,%2,%3}, [%4];"
                 : "=r"(a[0]), "=r"(a[1]), "=r"(a[2]), "=r"(a[3]) : "r"(addr));
}
__device__ __forceinline__ void mma16816(float d[4], const unsigned a[4],
                                         const unsigned b[2]) {
    asm volatile(
        "mma.sync.aligned.m16n8k16.row.col.f32.f16.f16.f32 "
        "{%0,%1,%2,%3},{%4,%5,%6,%7},{%8,%9},{%0,%1,%2,%3};"
        : "+f"(d[0]), "+f"(d[1]), "+f"(d[2]), "+f"(d[3])
        : "r"(a[0]), "r"(a[1]), "r"(a[2]), "r"(a[3]), "r"(b[0]), "r"(b[1]));
}
__device__ __forceinline__ void buildB(unsigned bf[4][2][2], const float* Wk,
                                       int lane) {
    int g = lane >> 2, t = lane & 3;
    #pragma unroll
    for (int nb = 0; nb < 4; ++nb) {
        int nn = nb * 8 + g;
        #pragma unroll
        for (int kb = 0; kb < 2; ++kb) {
            int k0 = 16 * kb + 2 * t;
            bf[nb][kb][0] = cvt_h2(__ldg(Wk + k0 * 32 + nn),
                                   __ldg(Wk + (k0 + 1) * 32 + nn));
            bf[nb][kb][1] = cvt_h2(__ldg(Wk + (k0 + 8) * 32 + nn),
                                   __ldg(Wk + (k0 + 9) * 32 + nn));
        }
    }
}

// ---------------------------------------------------------------------------
__global__ __launch_bounds__(256)
void build_rb(const int* __restrict__ nbr, int n)
{
    __shared__ int nsh[256 * 27];
    const int tid  = threadIdx.x;
    const int lane = tid & 31;
    const long long base = (long long)blockIdx.x * 256;

    for (int i = tid; i < 256 * 27; i += 256) {
        long long g = base * 27 + i;
        nsh[i] = (g < (long long)n * 27) ? nbr[g] : n;
    }
    __syncthreads();

    const int v = (int)(base + tid);
    const bool live = v < n;
    bool anyn = false;

    #pragma unroll 1
    for (int j = 0; j < NBK; ++j) {
        int k = (j < 13) ? j : j + 1;
        int u = nsh[tid * 27 + k];
        bool want = live && ((unsigned)u < (unsigned)n);
        anyn |= want;
        unsigned m = __ballot_sync(0xffffffffu, want);
        int rank = __popc(m & ((1u << lane) - 1));
        int leader = (m != 0u) ? (__ffs(m) - 1) : 0;
        int bp = 0;
        if (m != 0u && lane == leader) bp = atomicAdd(&g_kcnt[j], __popc(m));
        bp = __shfl_sync(0xffffffffu, bp, leader);
        int pos = bp + rank;
        if (want && pos < SEG) g_rb[j * SEG + pos] = make_int2(v, u);
    }

    if (live) g_flag[v] = anyn ? 1 : 0;
}

// ---------------------------------------------------------------------------
// FMA pair GEMM (nb_conv)
// ---------------------------------------------------------------------------
__device__ __forceinline__ void pair_gemm(const u64* f, const u64* wsp, int p,
                                          float& rA, float& rB)
{
    const ulonglong2* row = (const ulonglong2*)(f + p * 32);
    u64 aE = 0ull, aO = 0ull;
    #pragma unroll
    for (int c2 = 0; c2 < 16; ++c2) {
        ulonglong2 q = row[c2];
        fma2(aE, q.x, wsp[2 * c2]);
        fma2(aO, q.y, wsp[2 * c2 + 1]);
    }
    float2 e = unpack2(aE), o = unpack2(aO);
    rA = e.x + o.x;
    rB = e.y + o.y;
}

// ---------------------------------------------------------------------------
// neighbor taps: FMA pipeline, coalesced fp16x2 atomics
// ---------------------------------------------------------------------------
template <typename T>
__global__ __launch_bounds__(256)
void nb_conv(const T* __restrict__ x, const float* __restrict__ W,
             int kstride, int hoff, __half* __restrict__ acc, int n)
{
    __shared__ u64 ft[8 * 512];
    const int j   = blockIdx.x / BLKSEG;
    const int bis = blockIdx.x % BLKSEG;
    const int cnt = g_kcnt[j];
    if (bis * 256 >= cnt) return;

    const int k = (j < 13) ? j : j + 1;
    const float* Wk = W + (size_t)k * kstride + hoff;

    const int lane = threadIdx.x & 31;
    const int warp = threadIdx.x >> 5;

    u64 wsp[32];
    #pragma unroll
    for (int c = 0; c < 32; ++c) wsp[c] = splat2(__ldg(Wk + c * 32 + lane));

    const int eidx = bis * 256 + warp * 32 + lane;
    int2 e = (eidx < cnt) ? __ldg(&g_rb[j * SEG + eidx]) : make_int2(n, 0);

    u64* f = ft + warp * 512;
    #pragma unroll 4
    for (int p = 0; p < 16; ++p) {
        int uA = __shfl_sync(0xffffffffu, e.y, 2 * p);
        int uB = __shfl_sync(0xffffffffu, e.y, 2 * p + 1);
        f[p * 32 + lane] = pack2(loadf(x + (size_t)uA * 32 + lane),
                                 loadf(x + (size_t)uB * 32 + lane));
    }
    __syncwarp();

    #pragma unroll 2
    for (int p = 0; p < 16; ++p) {
        float rA, rB;
        pair_gemm(f, wsp, p, rA, rB);
        int vA = __shfl_sync(0xffffffffu, e.x, 2 * p);
        int vB = __shfl_sync(0xffffffffu, e.x, 2 * p + 1);
        float pA = __shfl_xor_sync(0xffffffffu, rA, 1);
        float pB = __shfl_xor_sync(0xffffffffu, rB, 1);
        unsigned hv;
        int v;
        if ((lane & 1) == 0) { hv = cvt_h2(rA, pA); v = vA; }
        else                 { hv = cvt_h2(pB, rB); v = vB; }
        redadd_h2(acc + (size_t)v * 32 + (lane & ~1), hv);
    }
}

// ---------------------------------------------------------------------------
// epilogue via HMMA with fused center tap; acc reads predicated on g_flag:
//   conv = [flag? acc : 0] + Wc0^T x0 (+ Wc1^T x1 for MODE 2)
//   MODE 0: y = relu(bn(conv)); 1: +res before relu; 2: +xred(cat(x0,x1)) after
// ---------------------------------------------------------------------------
template <int MODE, typename T0, typename TOUT>
__global__ __launch_bounds__(256)
void epi(const __half* __restrict__ acc, const float* __restrict__ bnp,
         const T0* __restrict__ x0, const float* __restrict__ Wc0,
         const __half* __restrict__ x1, const float* __restrict__ Wc1,
         const float* __restrict__ res,
         TOUT* __restrict__ out, int n)
{
    __shared__ __align__(16) char xsm[8 * 64 * ROWB];
    __shared__ float ssm[32], bsm[32];

    const int tid  = threadIdx.x;
    const int lane = tid & 31;
    const int warp = tid >> 5;
    const int g = lane >> 2, t = lane & 3;

    if (tid < 32) {
        float s = __ldg(bnp + tid) * rsqrtf(__ldg(bnp + 96 + tid) + 1e-3f);
        ssm[tid] = s;
        bsm[tid] = __ldg(bnp + 32 + tid) - __ldg(bnp + 64 + tid) * s;
    }
    __syncthreads();

    const int base = (blockIdx.x * 8 + warp) * 32;
    if (base >= n) return;

    // per-warp flag mask: bit i == voxel base+i has neighbor contributions
    unsigned fmask;
    {
        int vox = base + lane;
        bool f = (vox < n) && (g_flag[vox] != 0);
        fmask = __ballot_sync(0xffffffffu, f);
    }

    char* x0b = xsm + warp * (64 * ROWB);
    char* x1b = x0b + 32 * ROWB;

    {
        int vox = base + lane;
        int uu = (vox < n) ? vox : 0;
        stage_row(x0b, lane, x0 + (size_t)uu * 32);
        if (MODE == 2) stage_row(x1b, lane, x1 + (size_t)uu * 32);
    }
    __syncwarp();

    unsigned bf0[4][2][2];
    buildB(bf0, Wc0, lane);
    unsigned bf1[4][2][2];
    if (MODE == 2) buildB(bf1, Wc1, lane);

    #pragma unroll
    for (int mt = 0; mt < 2; ++mt) {
        unsigned a0[2][4];
        ldmA(a0[0], x0b, mt, 0, lane);
        ldmA(a0[1], x0b, mt, 1, lane);
        float d[4][4] = {};
        #pragma unroll
        for (int nb = 0; nb < 4; ++nb) {
            mma16816(d[nb], a0[0], bf0[nb][0]);
            mma16816(d[nb], a0[1], bf0[nb][1]);
        }
        if (MODE == 2) {
            unsigned a1[2][4];
            ldmA(a1[0], x1b, mt, 0, lane);
            ldmA(a1[1], x1b, mt, 1, lane);
            #pragma unroll
            for (int nb = 0; nb < 4; ++nb) {
                mma16816(d[nb], a1[0], bf1[nb][0]);
                mma16816(d[nb], a1[1], bf1[nb][1]);
            }
        }

        int v1 = base + mt * 16 + g;
        int v2 = v1 + 8;
        int u1 = (v1 < n) ? v1 : 0;
        int u2 = (v2 < n) ? v2 : 0;
        bool has1 = (fmask >> (mt * 16 + g)) & 1;
        bool has2 = (fmask >> (mt * 16 + g + 8)) & 1;

        #pragma unroll
        for (int nb = 0; nb < 4; ++nb) {
            int c0 = nb * 8 + 2 * t;
            float s0 = ssm[c0], s1 = ssm[c0 + 1];
            float b0 = bsm[c0], b1 = bsm[c0 + 1];

            #pragma unroll
            for (int rw = 0; rw < 2; ++rw) {
                int u = rw ? u2 : u1;
                int v = rw ? v2 : v1;
                bool has = rw ? has2 : has1;
                float dv0 = d[nb][rw * 2], dv1 = d[nb][rw * 2 + 1];
                float2 a2 = make_float2(0.0f, 0.0f);
                if (has)
                    a2 = h2f(*(const unsigned*)__builtin_assume_aligned(
                             (const void*)(acc + (size_t)u * 32 + c0), 4));
                float y0 = (a2.x + dv0) * s0 + b0;
                float y1 = (a2.y + dv1) * s1 + b1;
                if (MODE == 1) {
                    float2 rr = __ldg((const float2*)(res + (size_t)u * 32 + c0));
                    y0 += rr.x; y1 += rr.y;
                }
                y0 = fmaxf(y0, 0.0f);
                y1 = fmaxf(y1, 0.0f);
                if (MODE == 2) {
                    if (nb < 2) {
                        float4 q = __ldg((const float4*)((const float*)x0 +
                                         (size_t)u * 32 + 2 * c0));
                        y0 += q.x + q.y;
                        y1 += q.z + q.w;
                    } else {
                        const __half2* hp = (const __half2*)(x1 +
                                            (size_t)u * 32 + (2 * c0 - 32));
                        float2 qa = __half22float2(__ldg(hp));
                        float2 qb = __half22float2(__ldg(hp + 1));
                        y0 += qa.x + qa.y;
                        y1 += qb.x + qb.y;
                    }
                }
                if (v < n) storepair(out + (size_t)v * 32 + c0, y0, y1);
            }
        }
    }
}

// ---------------------------------------------------------------------------
extern "C" void kernel_launch(void* const* d_in, const int* in_sizes, int n_in,
                              void* d_out, int out_size)
{
    const float* lat  = (const float*)d_in[0];
    const float* bot  = (const float*)d_in[1];
    const float* Wt1  = (const float*)d_in[2];
    const float* bnt1 = (const float*)d_in[3];
    const float* Wt2  = (const float*)d_in[4];
    const float* bnt2 = (const float*)d_in[5];
    const float* Wm   = (const float*)d_in[6];
    const float* bnm  = (const float*)d_in[7];
    const float* Wi   = (const float*)d_in[8];
    const float* bni  = (const float*)d_in[9];
    const int*   nbr  = (const int*)d_in[10];

    const int n = in_sizes[0] / NC;

    __half *accb, *h1, *h2, *h3;
    int* kcnt;
    cudaGetSymbolAddress((void**)&accb, g_acc);
    cudaGetSymbolAddress((void**)&h1, g_h1);
    cudaGetSymbolAddress((void**)&h2, g_h2);
    cudaGetSymbolAddress((void**)&h3, g_h3);
    cudaGetSymbolAddress((void**)&kcnt, g_kcnt);

    __half* a1 = accb;
    __half* a2 = accb + 1 * ASTRIDE;
    __half* a3 = accb + 2 * ASTRIDE;
    __half* a4 = accb + 3 * ASTRIDE;

    static cudaStream_t s1 = nullptr, s2 = nullptr;
    static cudaEvent_t e0 = nullptr, eB = nullptr, e2 = nullptr;
    static cudaEvent_t em1 = nullptr, em2 = nullptr, em3 = nullptr, em4 = nullptr;
    if (!s1) {
        cudaStreamCreateWithFlags(&s1, cudaStreamNonBlocking);
        cudaStreamCreateWithFlags(&s2, cudaStreamNonBlocking);
        cudaEventCreateWithFlags(&e0, cudaEventDisableTiming);
        cudaEventCreateWithFlags(&eB, cudaEventDisableTiming);
        cudaEventCreateWithFlags(&e2, cudaEventDisableTiming);
        cudaEventCreateWithFlags(&em1, cudaEventDisableTiming);
        cudaEventCreateWithFlags(&em2, cudaEventDisableTiming);
        cudaEventCreateWithFlags(&em3, cudaEventDisableTiming);
        cudaEventCreateWithFlags(&em4, cudaEventDisableTiming);
    }

    const int gridC = (n + 255) / 256;
    const int gridN = NBK * BLKSEG;

    cudaMemsetAsync(kcnt, 0, 32 * sizeof(int), 0);
    cudaEventRecord(e0, 0);
    cudaStreamWaitEvent(s1, e0, 0);
    cudaMemsetAsync(a1, 0, ACCBYTES, s1); cudaEventRecord(em1, s1);
    cudaMemsetAsync(a3, 0, ACCBYTES, s1); cudaEventRecord(em3, s1);
    cudaMemsetAsync(a2, 0, ACCBYTES, s1); cudaEventRecord(em2, s1);
    cudaMemsetAsync(a4, 0, ACCBYTES, s1); cudaEventRecord(em4, s1);

    build_rb<<<gridC, 256>>>(nbr, n);
    cudaEventRecord(eB, 0);

    // fork: conv_m's bot-half neighbor pass overlaps conv1/conv2
    cudaStreamWaitEvent(s2, eB, 0);
    cudaStreamWaitEvent(s2, em3, 0);
    nb_conv<float><<<gridN, 256, 0, s2>>>(bot, Wm, 2048, 0, a3, n);
    cudaEventRecord(e2, s2);

    // conv1
    cudaStreamWaitEvent(0, em1, 0);
    nb_conv<float><<<gridN, 256>>>(lat, Wt1, 1024, 0, a1, n);
    epi<0, float, __half><<<gridC, 256>>>(a1, bnt1, lat, Wt1 + 13 * 1024,
                                          nullptr, nullptr, nullptr, h1, n);

    // conv2 (residual = lat fp32)
    cudaStreamWaitEvent(0, em2, 0);
    nb_conv<__half><<<gridN, 256>>>(h1, Wt2, 1024, 0, a2, n);
    epi<1, __half, __half><<<gridC, 256>>>(a2, bnt2, h1, Wt2 + 13 * 1024,
                                           nullptr, nullptr, lat, h2, n);

    // conv_m
    nb_conv<__half><<<gridN, 256>>>(h2, Wm, 2048, 1024, a3, n);
    cudaStreamWaitEvent(0, e2, 0);
    epi<2, float, __half><<<gridC, 256>>>(a3, bnm, bot, Wm + 13 * 2048,
                                          h2, Wm + 13 * 2048 + 1024, nullptr, h3, n);

    // conv_inv
    cudaStreamWaitEvent(0, em4, 0);
    nb_conv<__half><<<gridN, 256>>>(h3, Wi, 1024, 0, a4, n);
    epi<0, __half, float><<<gridC, 256>>>(a4, bni, h3, Wi + 13 * 1024,
                                          nullptr, nullptr, nullptr, (float*)d_out, n);
}

// round 15
// speedup vs baseline: 1.1182x; 1.0215x over previous
#include <cuda_runtime.h>
#include <cuda_fp16.h>

// ---------------------------------------------------------------------------
// UNetV2 on GB300 (R15 = R14 + hoisted predicated acc preloads in epi):
//  - nb_conv: FMA f32x2 gather-GEMM, coalesced fp16x2 atomics
//  - epi: acc rows preloaded up-front (MLP~16, predicated on has-neighbors
//    flag), HMMA center tap, fragment-order IO, 128-thread blocks
// ---------------------------------------------------------------------------

#define MAXN 500000
#define NC   32
#define SEG  16384
#define NBK  26
#define BLKSEG 64
#define ASTRIDE ((size_t)(MAXN + 1) * NC)
#define ACCBYTES (ASTRIDE * sizeof(__half))
#define ROWB 80

static __device__ __half g_acc[4 * ASTRIDE];
static __device__ __half g_h1[MAXN * NC];
static __device__ __half g_h2[MAXN * NC];
static __device__ __half g_h3[MAXN * NC];
static __device__ int2   g_rb[NBK * SEG];
static __device__ int    g_kcnt[32];
static __device__ unsigned char g_flag[MAXN + 256];

typedef unsigned long long u64;

__device__ __forceinline__ u64 splat2(float a) {
    u64 r; asm("mov.b64 %0, {%1, %1};" : "=l"(r) : "f"(a)); return r;
}
__device__ __forceinline__ u64 pack2(float a, float b) {
    u64 r; asm("mov.b64 %0, {%1, %2};" : "=l"(r) : "f"(a), "f"(b)); return r;
}
__device__ __forceinline__ void fma2(u64& d, u64 a, u64 b) {
    asm("fma.rn.f32x2 %0, %1, %2, %3;" : "=l"(d) : "l"(a), "l"(b), "l"(d));
}
__device__ __forceinline__ float2 unpack2(u64 a) {
    float2 r; asm("mov.b64 {%0, %1}, %2;" : "=f"(r.x), "=f"(r.y) : "l"(a)); return r;
}
__device__ __forceinline__ unsigned cvt_h2(float lo, float hi) {
    unsigned r;
    asm("cvt.rn.f16x2.f32 %0, %1, %2;" : "=r"(r) : "f"(hi), "f"(lo));
    return r;
}
__device__ __forceinline__ float2 h2f(unsigned u) {
    return __half22float2(*(__half2*)&u);
}
__device__ __forceinline__ void redadd_h2(__half* p, unsigned hv) {
    asm volatile("red.global.add.noftz.f16x2 [%0], %1;" :: "l"(p), "r"(hv) : "memory");
}
__device__ __forceinline__ float loadf(const float* p)  { return __ldg(p); }
__device__ __forceinline__ float loadf(const __half* p) { return __half2float(__ldg(p)); }
__device__ __forceinline__ void storepair(float* p, float y0, float y1) {
    *(float2*)p = make_float2(y0, y1);
}
__device__ __forceinline__ void storepair(__half* p, float y0, float y1) {
    *(__half2*)p = __floats2half2_rn(y0, y1);
}

// ---------------------------------------------------------------------------
// HMMA helpers
// ---------------------------------------------------------------------------
__device__ __forceinline__ void stage_row(char* wbase, int r, const __half* row) {
    const uint4* s = (const uint4*)row;
    int sw = (r >> 3) & 3;
    char* rb = wbase + r * ROWB;
    #pragma unroll
    for (int c = 0; c < 4; ++c)
        *(uint4*)(rb + ((c ^ sw) << 4)) = __ldg(s + c);
}
__device__ __forceinline__ void stage_row(char* wbase, int r, const float* row) {
    const float4* s = (const float4*)row;
    int sw = (r >> 3) & 3;
    char* rb = wbase + r * ROWB;
    #pragma unroll
    for (int c = 0; c < 4; ++c) {
        float4 f0 = __ldg(s + 2 * c);
        float4 f1 = __ldg(s + 2 * c + 1);
        uint4 v;
        v.x = cvt_h2(f0.x, f0.y); v.y = cvt_h2(f0.z, f0.w);
        v.z = cvt_h2(f1.x, f1.y); v.w = cvt_h2(f1.z, f1.w);
        *(uint4*)(rb + ((c ^ sw) << 4)) = v;
    }
}
__device__ __forceinline__ void ldmA(unsigned a[4], const char* wbase, int mt,
                                     int kb, int lane) {
    int r  = mt * 16 + (lane & 15);
    int lc = 2 * kb + (lane >> 4);
    unsigned addr = (unsigned)__cvta_generic_to_shared(
        wbase + r * ROWB + ((lc ^ ((r >> 3) & 3)) << 4));
    asm volatile("ldmatrix.sync.aligned.m8n8.x4.shared.b16 {%0,%1,%2,%3}, [%4];"
                 : "=r"(a[0]), "=r"(a[1]), "=r"(a[2]), "=r"(a[3]) : "r"(addr));
}
__device__ __forceinline__ void mma16816(float d[4], const unsigned a[4],
                                         const unsigned b[2]) {
    asm volatile(
        "mma.sync.aligned.m16n8k16.row.col.f32.f16.f16.f32 "
        "{%0,%1,%2,%3},{%4,%5,%6,%7},{%8,%9},{%0,%1,%2,%3};"
        : "+f"(d[0]), "+f"(d[1]), "+f"(d[2]), "+f"(d[3])
        : "r"(a[0]), "r"(a[1]), "r"(a[2]), "r"(a[3]), "r"(b[0]), "r"(b[1]));
}
__device__ __forceinline__ void buildB(unsigned bf[4][2][2], const float* Wk,
                                       int lane) {
    int g = lane >> 2, t = lane & 3;
    #pragma unroll
    for (int nb = 0; nb < 4; ++nb) {
        int nn = nb * 8 + g;
        #pragma unroll
        for (int kb = 0; kb < 2; ++kb) {
            int k0 = 16 * kb + 2 * t;
            bf[nb][kb][0] = cvt_h2(__ldg(Wk + k0 * 32 + nn),
                                   __ldg(Wk + (k0 + 1) * 32 + nn));
            bf[nb][kb][1] = cvt_h2(__ldg(Wk + (k0 + 8) * 32 + nn),
                                   __ldg(Wk + (k0 + 9) * 32 + nn));
        }
    }
}

// ---------------------------------------------------------------------------
__global__ __launch_bounds__(256)
void build_rb(const int* __restrict__ nbr, int n)
{
    __shared__ int nsh[256 * 27];
    const int tid  = threadIdx.x;
    const int lane = tid & 31;
    const long long base = (long long)blockIdx.x * 256;

    for (int i = tid; i < 256 * 27; i += 256) {
        long long g = base * 27 + i;
        nsh[i] = (g < (long long)n * 27) ? nbr[g] : n;
    }
    __syncthreads();

    const int v = (int)(base + tid);
    const bool live = v < n;
    bool anyn = false;

    #pragma unroll 1
    for (int j = 0; j < NBK; ++j) {
        int k = (j < 13) ? j : j + 1;
        int u = nsh[tid * 27 + k];
        bool want = live && ((unsigned)u < (unsigned)n);
        anyn |= want;
        unsigned m = __ballot_sync(0xffffffffu, want);
        int rank = __popc(m & ((1u << lane) - 1));
        int leader = (m != 0u) ? (__ffs(m) - 1) : 0;
        int bp = 0;
        if (m != 0u && lane == leader) bp = atomicAdd(&g_kcnt[j], __popc(m));
        bp = __shfl_sync(0xffffffffu, bp, leader);
        int pos = bp + rank;
        if (want && pos < SEG) g_rb[j * SEG + pos] = make_int2(v, u);
    }

    if (live) g_flag[v] = anyn ? 1 : 0;
}

// ---------------------------------------------------------------------------
// FMA pair GEMM (nb_conv)
// ---------------------------------------------------------------------------
__device__ __forceinline__ void pair_gemm(const u64* f, const u64* wsp, int p,
                                          float& rA, float& rB)
{
    const ulonglong2* row = (const ulonglong2*)(f + p * 32);
    u64 aE = 0ull, aO = 0ull;
    #pragma unroll
    for (int c2 = 0; c2 < 16; ++c2) {
        ulonglong2 q = row[c2];
        fma2(aE, q.x, wsp[2 * c2]);
        fma2(aO, q.y, wsp[2 * c2 + 1]);
    }
    float2 e = unpack2(aE), o = unpack2(aO);
    rA = e.x + o.x;
    rB = e.y + o.y;
}

// ---------------------------------------------------------------------------
// neighbor taps: FMA pipeline, coalesced fp16x2 atomics
// ---------------------------------------------------------------------------
template <typename T>
__global__ __launch_bounds__(256)
void nb_conv(const T* __restrict__ x, const float* __restrict__ W,
             int kstride, int hoff, __half* __restrict__ acc, int n)
{
    __shared__ u64 ft[8 * 512];
    const int j   = blockIdx.x / BLKSEG;
    const int bis = blockIdx.x % BLKSEG;
    const int cnt = g_kcnt[j];
    if (bis * 256 >= cnt) return;

    const int k = (j < 13) ? j : j + 1;
    const float* Wk = W + (size_t)k * kstride + hoff;

    const int lane = threadIdx.x & 31;
    const int warp = threadIdx.x >> 5;

    u64 wsp[32];
    #pragma unroll
    for (int c = 0; c < 32; ++c) wsp[c] = splat2(__ldg(Wk + c * 32 + lane));

    const int eidx = bis * 256 + warp * 32 + lane;
    int2 e = (eidx < cnt) ? __ldg(&g_rb[j * SEG + eidx]) : make_int2(n, 0);

    u64* f = ft + warp * 512;
    #pragma unroll 4
    for (int p = 0; p < 16; ++p) {
        int uA = __shfl_sync(0xffffffffu, e.y, 2 * p);
        int uB = __shfl_sync(0xffffffffu, e.y, 2 * p + 1);
        f[p * 32 + lane] = pack2(loadf(x + (size_t)uA * 32 + lane),
                                 loadf(x + (size_t)uB * 32 + lane));
    }
    __syncwarp();

    #pragma unroll 2
    for (int p = 0; p < 16; ++p) {
        float rA, rB;
        pair_gemm(f, wsp, p, rA, rB);
        int vA = __shfl_sync(0xffffffffu, e.x, 2 * p);
        int vB = __shfl_sync(0xffffffffu, e.x, 2 * p + 1);
        float pA = __shfl_xor_sync(0xffffffffu, rA, 1);
        float pB = __shfl_xor_sync(0xffffffffu, rB, 1);
        unsigned hv;
        int v;
        if ((lane & 1) == 0) { hv = cvt_h2(rA, pA); v = vA; }
        else                 { hv = cvt_h2(pB, rB); v = vB; }
        redadd_h2(acc + (size_t)v * 32 + (lane & ~1), hv);
    }
}

// ---------------------------------------------------------------------------
// epilogue via HMMA, acc rows PRELOADED up-front (predicated on g_flag):
//   conv = [flag? acc : 0] + Wc0^T x0 (+ Wc1^T x1 for MODE 2)
//   MODE 0: y = relu(bn(conv)); 1: +res before relu; 2: +xred(cat(x0,x1)) after
// ---------------------------------------------------------------------------
template <int MODE, typename T0, typename TOUT>
__global__ __launch_bounds__(128)
void epi(const __half* __restrict__ acc, const float* __restrict__ bnp,
         const T0* __restrict__ x0, const float* __restrict__ Wc0,
         const __half* __restrict__ x1, const float* __restrict__ Wc1,
         const float* __restrict__ res,
         TOUT* __restrict__ out, int n)
{
    __shared__ __align__(16) char xsm[4 * 64 * ROWB];
    __shared__ float ssm[32], bsm[32];

    const int tid  = threadIdx.x;
    const int lane = tid & 31;
    const int warp = tid >> 5;
    const int g = lane >> 2, t = lane & 3;

    if (tid < 32) {
        float s = __ldg(bnp + tid) * rsqrtf(__ldg(bnp + 96 + tid) + 1e-3f);
        ssm[tid] = s;
        bsm[tid] = __ldg(bnp + 32 + tid) - __ldg(bnp + 64 + tid) * s;
    }
    __syncthreads();

    const int base = (blockIdx.x * 4 + warp) * 32;
    if (base >= n) return;

    // per-warp flag mask
    unsigned fmask;
    {
        int vox = base + lane;
        bool f = (vox < n) && (g_flag[vox] != 0);
        fmask = __ballot_sync(0xffffffffu, f);
    }

    // ---- hoisted predicated acc preloads: 16 LDG.32 back-to-back (MLP) ----
    unsigned accbits[16];
    #pragma unroll
    for (int mt = 0; mt < 2; ++mt) {
        #pragma unroll
        for (int rw = 0; rw < 2; ++rw) {
            int row = mt * 16 + 8 * rw + g;
            int vv = base + row;
            int u = (vv < n) ? vv : 0;
            bool has = (fmask >> row) & 1;
            #pragma unroll
            for (int nb = 0; nb < 4; ++nb) {
                unsigned b = 0;
                if (has)
                    b = *(const unsigned*)(acc + (size_t)u * 32 + nb * 8 + 2 * t);
                accbits[(mt * 2 + rw) * 4 + nb] = b;
            }
        }
    }

    char* x0b = xsm + warp * (64 * ROWB);
    char* x1b = x0b + 32 * ROWB;

    {
        int vox = base + lane;
        int uu = (vox < n) ? vox : 0;
        stage_row(x0b, lane, x0 + (size_t)uu * 32);
        if (MODE == 2) stage_row(x1b, lane, x1 + (size_t)uu * 32);
    }
    __syncwarp();

    unsigned bf0[4][2][2];
    buildB(bf0, Wc0, lane);
    unsigned bf1[4][2][2];
    if (MODE == 2) buildB(bf1, Wc1, lane);

    #pragma unroll
    for (int mt = 0; mt < 2; ++mt) {
        unsigned a0[2][4];
        ldmA(a0[0], x0b, mt, 0, lane);
        ldmA(a0[1], x0b, mt, 1, lane);
        float d[4][4] = {};
        #pragma unroll
        for (int nb = 0; nb < 4; ++nb) {
            mma16816(d[nb], a0[0], bf0[nb][0]);
            mma16816(d[nb], a0[1], bf0[nb][1]);
        }
        if (MODE == 2) {
            unsigned a1[2][4];
            ldmA(a1[0], x1b, mt, 0, lane);
            ldmA(a1[1], x1b, mt, 1, lane);
            #pragma unroll
            for (int nb = 0; nb < 4; ++nb) {
                mma16816(d[nb], a1[0], bf1[nb][0]);
                mma16816(d[nb], a1[1], bf1[nb][1]);
            }
        }

        int v1 = base + mt * 16 + g;
        int v2 = v1 + 8;
        int u1 = (v1 < n) ? v1 : 0;
        int u2 = (v2 < n) ? v2 : 0;

        #pragma unroll
        for (int nb = 0; nb < 4; ++nb) {
            int c0 = nb * 8 + 2 * t;
            float s0 = ssm[c0], s1 = ssm[c0 + 1];
            float b0 = bsm[c0], b1 = bsm[c0 + 1];

            #pragma unroll
            for (int rw = 0; rw < 2; ++rw) {
                int u = rw ? u2 : u1;
                int v = rw ? v2 : v1;
                float dv0 = d[nb][rw * 2], dv1 = d[nb][rw * 2 + 1];
                float2 a2 = h2f(accbits[(mt * 2 + rw) * 4 + nb]);
                float y0 = (a2.x + dv0) * s0 + b0;
                float y1 = (a2.y + dv1) * s1 + b1;
                if (MODE == 1) {
                    float2 rr = __ldg((const float2*)(res + (size_t)u * 32 + c0));
                    y0 += rr.x; y1 += rr.y;
                }
                y0 = fmaxf(y0, 0.0f);
                y1 = fmaxf(y1, 0.0f);
                if (MODE == 2) {
                    if (nb < 2) {
                        float4 q = __ldg((const float4*)((const float*)x0 +
                                         (size_t)u * 32 + 2 * c0));
                        y0 += q.x + q.y;
                        y1 += q.z + q.w;
                    } else {
                        const __half2* hp = (const __half2*)(x1 +
                                            (size_t)u * 32 + (2 * c0 - 32));
                        float2 qa = __half22float2(__ldg(hp));
                        float2 qb = __half22float2(__ldg(hp + 1));
                        y0 += qa.x + qa.y;
                        y1 += qb.x + qb.y;
                    }
                }
                if (v < n) storepair(out + (size_t)v * 32 + c0, y0, y1);
            }
        }
    }
}

// ---------------------------------------------------------------------------
extern "C" void kernel_launch(void* const* d_in, const int* in_sizes, int n_in,
                              void* d_out, int out_size)
{
    const float* lat  = (const float*)d_in[0];
    const float* bot  = (const float*)d_in[1];
    const float* Wt1  = (const float*)d_in[2];
    const float* bnt1 = (const float*)d_in[3];
    const float* Wt2  = (const float*)d_in[4];
    const float* bnt2 = (const float*)d_in[5];
    const float* Wm   = (const float*)d_in[6];
    const float* bnm  = (const float*)d_in[7];
    const float* Wi   = (const float*)d_in[8];
    const float* bni  = (const float*)d_in[9];
    const int*   nbr  = (const int*)d_in[10];

    const int n = in_sizes[0] / NC;

    __half *accb, *h1, *h2, *h3;
    int* kcnt;
    cudaGetSymbolAddress((void**)&accb, g_acc);
    cudaGetSymbolAddress((void**)&h1, g_h1);
    cudaGetSymbolAddress((void**)&h2, g_h2);
    cudaGetSymbolAddress((void**)&h3, g_h3);
    cudaGetSymbolAddress((void**)&kcnt, g_kcnt);

    __half* a1 = accb;
    __half* a2 = accb + 1 * ASTRIDE;
    __half* a3 = accb + 2 * ASTRIDE;
    __half* a4 = accb + 3 * ASTRIDE;

    static cudaStream_t s1 = nullptr, s2 = nullptr;
    static cudaEvent_t e0 = nullptr, eB = nullptr, e2 = nullptr;
    static cudaEvent_t em1 = nullptr, em2 = nullptr, em3 = nullptr, em4 = nullptr;
    if (!s1) {
        cudaStreamCreateWithFlags(&s1, cudaStreamNonBlocking);
        cudaStreamCreateWithFlags(&s2, cudaStreamNonBlocking);
        cudaEventCreateWithFlags(&e0, cudaEventDisableTiming);
        cudaEventCreateWithFlags(&eB, cudaEventDisableTiming);
        cudaEventCreateWithFlags(&e2, cudaEventDisableTiming);
        cudaEventCreateWithFlags(&em1, cudaEventDisableTiming);
        cudaEventCreateWithFlags(&em2, cudaEventDisableTiming);
        cudaEventCreateWithFlags(&em3, cudaEventDisableTiming);
        cudaEventCreateWithFlags(&em4, cudaEventDisableTiming);
    }

    const int gridC = (n + 255) / 256;
    const int gridE = (n + 127) / 128;
    const int gridN = NBK * BLKSEG;

    cudaMemsetAsync(kcnt, 0, 32 * sizeof(int), 0);
    cudaEventRecord(e0, 0);
    cudaStreamWaitEvent(s1, e0, 0);
    cudaMemsetAsync(a1, 0, ACCBYTES, s1); cudaEventRecord(em1, s1);
    cudaMemsetAsync(a3, 0, ACCBYTES, s1); cudaEventRecord(em3, s1);
    cudaMemsetAsync(a2, 0, ACCBYTES, s1); cudaEventRecord(em2, s1);
    cudaMemsetAsync(a4, 0, ACCBYTES, s1); cudaEventRecord(em4, s1);

    build_rb<<<gridC, 256>>>(nbr, n);
    cudaEventRecord(eB, 0);

    // fork: conv_m's bot-half neighbor pass overlaps conv1/conv2
    cudaStreamWaitEvent(s2, eB, 0);
    cudaStreamWaitEvent(s2, em3, 0);
    nb_conv<float><<<gridN, 256, 0, s2>>>(bot, Wm, 2048, 0, a3, n);
    cudaEventRecord(e2, s2);

    // conv1
    cudaStreamWaitEvent(0, em1, 0);
    nb_conv<float><<<gridN, 256>>>(lat, Wt1, 1024, 0, a1, n);
    epi<0, float, __half><<<gridE, 128>>>(a1, bnt1, lat, Wt1 + 13 * 1024,
                                          nullptr, nullptr, nullptr, h1, n);

    // conv2 (residual = lat fp32)
    cudaStreamWaitEvent(0, em2, 0);
    nb_conv<__half><<<gridN, 256>>>(h1, Wt2, 1024, 0, a2, n);
    epi<1, __half, __half><<<gridE, 128>>>(a2, bnt2, h1, Wt2 + 13 * 1024,
                                           nullptr, nullptr, lat, h2, n);

    // conv_m
    nb_conv<__half><<<gridN, 256>>>(h2, Wm, 2048, 1024, a3, n);
    cudaStreamWaitEvent(0, e2, 0);
    epi<2, float, __half><<<gridE, 128>>>(a3, bnm, bot, Wm + 13 * 2048,
                                          h2, Wm + 13 * 2048 + 1024, nullptr, h3, n);

    // conv_inv
    cudaStreamWaitEvent(0, em4, 0);
    nb_conv<__half><<<gridN, 256>>>(h3, Wi, 1024, 0, a4, n);
    epi<0, __half, float><<<gridE, 128>>>(a4, bni, h3, Wi + 13 * 1024,
                                          nullptr, nullptr, nullptr, (float*)d_out, n);
}

// round 16
// speedup vs baseline: 1.1759x; 1.0516x over previous
#include <cuda_runtime.h>
#include <cuda_fp16.h>

// ---------------------------------------------------------------------------
// UNetV2 on GB300 (R16 = R15 + flat coalesced tile staging in epi):
//  - nb_conv: FMA f32x2 gather-GEMM, coalesced fp16x2 atomics
//  - epi: acc rows preloaded up-front (predicated on has-neighbors flag),
//    x0/x1 tiles staged with flat coalesced loads (4 lines/instr vs 32),
//    HMMA center tap, fragment-order IO, 128-thread blocks
// ---------------------------------------------------------------------------

#define MAXN 500000
#define NC   32
#define SEG  16384
#define NBK  26
#define BLKSEG 64
#define ASTRIDE ((size_t)(MAXN + 1) * NC)
#define ACCBYTES (ASTRIDE * sizeof(__half))
#define ROWB 80

static __device__ __half g_acc[4 * ASTRIDE];
static __device__ __half g_h1[MAXN * NC];
static __device__ __half g_h2[MAXN * NC];
static __device__ __half g_h3[MAXN * NC];
static __device__ int2   g_rb[NBK * SEG];
static __device__ int    g_kcnt[32];
static __device__ unsigned char g_flag[MAXN + 256];

typedef unsigned long long u64;

__device__ __forceinline__ u64 splat2(float a) {
    u64 r; asm("mov.b64 %0, {%1, %1};" : "=l"(r) : "f"(a)); return r;
}
__device__ __forceinline__ u64 pack2(float a, float b) {
    u64 r; asm("mov.b64 %0, {%1, %2};" : "=l"(r) : "f"(a), "f"(b)); return r;
}
__device__ __forceinline__ void fma2(u64& d, u64 a, u64 b) {
    asm("fma.rn.f32x2 %0, %1, %2, %3;" : "=l"(d) : "l"(a), "l"(b), "l"(d));
}
__device__ __forceinline__ float2 unpack2(u64 a) {
    float2 r; asm("mov.b64 {%0, %1}, %2;" : "=f"(r.x), "=f"(r.y) : "l"(a)); return r;
}
__device__ __forceinline__ unsigned cvt_h2(float lo, float hi) {
    unsigned r;
    asm("cvt.rn.f16x2.f32 %0, %1, %2;" : "=r"(r) : "f"(hi), "f"(lo));
    return r;
}
__device__ __forceinline__ float2 h2f(unsigned u) {
    return __half22float2(*(__half2*)&u);
}
__device__ __forceinline__ void redadd_h2(__half* p, unsigned hv) {
    asm volatile("red.global.add.noftz.f16x2 [%0], %1;" :: "l"(p), "r"(hv) : "memory");
}
__device__ __forceinline__ float loadf(const float* p)  { return __ldg(p); }
__device__ __forceinline__ float loadf(const __half* p) { return __half2float(__ldg(p)); }
__device__ __forceinline__ void storepair(float* p, float y0, float y1) {
    *(float2*)p = make_float2(y0, y1);
}
__device__ __forceinline__ void storepair(__half* p, float y0, float y1) {
    *(__half2*)p = __floats2half2_rn(y0, y1);
}

// ---------------------------------------------------------------------------
// smem tile staging
// ---------------------------------------------------------------------------
// per-row fallback (edge tiles)
__device__ __forceinline__ void stage_row(char* wbase, int r, const __half* row) {
    const uint4* s = (const uint4*)row;
    int sw = (r >> 3) & 3;
    char* rb = wbase + r * ROWB;
    #pragma unroll
    for (int c = 0; c < 4; ++c)
        *(uint4*)(rb + ((c ^ sw) << 4)) = __ldg(s + c);
}
__device__ __forceinline__ void stage_row(char* wbase, int r, const float* row) {
    const float4* s = (const float4*)row;
    int sw = (r >> 3) & 3;
    char* rb = wbase + r * ROWB;
    #pragma unroll
    for (int c = 0; c < 4; ++c) {
        float4 f0 = __ldg(s + 2 * c);
        float4 f1 = __ldg(s + 2 * c + 1);
        uint4 v;
        v.x = cvt_h2(f0.x, f0.y); v.y = cvt_h2(f0.z, f0.w);
        v.z = cvt_h2(f1.x, f1.y); v.w = cvt_h2(f1.z, f1.w);
        *(uint4*)(rb + ((c ^ sw) << 4)) = v;
    }
}

// flat coalesced full-tile staging (rows base..base+31 contiguous in gmem)
__device__ __forceinline__ void stage_tile(char* wbase, const __half* x,
                                           int base, int lane) {
    const uint4* src = (const uint4*)(x + (size_t)base * 32);   // 128 uint4
    #pragma unroll
    for (int k2 = 0; k2 < 4; ++k2) {
        int idx = k2 * 32 + lane;
        uint4 v = __ldg(src + idx);
        int row = idx >> 2;          // 4 uint4 per 64B fp16 row
        int cw  = idx & 3;
        int sw  = (row >> 3) & 3;
        *(uint4*)(wbase + row * ROWB + ((cw ^ sw) << 4)) = v;
    }
}
__device__ __forceinline__ void stage_tile(char* wbase, const float* x,
                                           int base, int lane) {
    const float4* src = (const float4*)(x + (size_t)base * 32); // 256 float4
    #pragma unroll
    for (int k2 = 0; k2 < 8; ++k2) {
        int idx = k2 * 32 + lane;
        float4 f = __ldg(src + idx);
        uint2 v = make_uint2(cvt_h2(f.x, f.y), cvt_h2(f.z, f.w));
        int row = idx >> 3;          // 8 float4 per 128B fp32 row
        int q   = idx & 7;
        int cw  = q >> 1;
        int h   = q & 1;
        int sw  = (row >> 3) & 3;
        *(uint2*)(wbase + row * ROWB + ((cw ^ sw) << 4) + h * 8) = v;
    }
}

__device__ __forceinline__ void ldmA(unsigned a[4], const char* wbase, int mt,
                                     int kb, int lane) {
    int r  = mt * 16 + (lane & 15);
    int lc = 2 * kb + (lane >> 4);
    unsigned addr = (unsigned)__cvta_generic_to_shared(
        wbase + r * ROWB + ((lc ^ ((r >> 3) & 3)) << 4));
    asm volatile("ldmatrix.sync.aligned.m8n8.x4.shared.b16 {%0,%1,%2,%3}, [%4];"
                 : "=r"(a[0]), "=r"(a[1]), "=r"(a[2]), "=r"(a[3]) : "r"(addr));
}
__device__ __forceinline__ void mma16816(float d[4], const unsigned a[4],
                                         const unsigned b[2]) {
    asm volatile(
        "mma.sync.aligned.m16n8k16.row.col.f32.f16.f16.f32 "
        "{%0,%1,%2,%3},{%4,%5,%6,%7},{%8,%9},{%0,%1,%2,%3};"
        : "+f"(d[0]), "+f"(d[1]), "+f"(d[2]), "+f"(d[3])
        : "r"(a[0]), "r"(a[1]), "r"(a[2]), "r"(a[3]), "r"(b[0]), "r"(b[1]));
}
__device__ __forceinline__ void buildB(unsigned bf[4][2][2], const float* Wk,
                                       int lane) {
    int g = lane >> 2, t = lane & 3;
    #pragma unroll
    for (int nb = 0; nb < 4; ++nb) {
        int nn = nb * 8 + g;
        #pragma unroll
        for (int kb = 0; kb < 2; ++kb) {
            int k0 = 16 * kb + 2 * t;
            bf[nb][kb][0] = cvt_h2(__ldg(Wk + k0 * 32 + nn),
                                   __ldg(Wk + (k0 + 1) * 32 + nn));
            bf[nb][kb][1] = cvt_h2(__ldg(Wk + (k0 + 8) * 32 + nn),
                                   __ldg(Wk + (k0 + 9) * 32 + nn));
        }
    }
}

// ---------------------------------------------------------------------------
__global__ __launch_bounds__(256)
void build_rb(const int* __restrict__ nbr, int n)
{
    __shared__ int nsh[256 * 27];
    const int tid  = threadIdx.x;
    const int lane = tid & 31;
    const long long base = (long long)blockIdx.x * 256;

    for (int i = tid; i < 256 * 27; i += 256) {
        long long g = base * 27 + i;
        nsh[i] = (g < (long long)n * 27) ? nbr[g] : n;
    }
    __syncthreads();

    const int v = (int)(base + tid);
    const bool live = v < n;
    bool anyn = false;

    #pragma unroll 1
    for (int j = 0; j < NBK; ++j) {
        int k = (j < 13) ? j : j + 1;
        int u = nsh[tid * 27 + k];
        bool want = live && ((unsigned)u < (unsigned)n);
        anyn |= want;
        unsigned m = __ballot_sync(0xffffffffu, want);
        int rank = __popc(m & ((1u << lane) - 1));
        int leader = (m != 0u) ? (__ffs(m) - 1) : 0;
        int bp = 0;
        if (m != 0u && lane == leader) bp = atomicAdd(&g_kcnt[j], __popc(m));
        bp = __shfl_sync(0xffffffffu, bp, leader);
        int pos = bp + rank;
        if (want && pos < SEG) g_rb[j * SEG + pos] = make_int2(v, u);
    }

    if (live) g_flag[v] = anyn ? 1 : 0;
}

// ---------------------------------------------------------------------------
// FMA pair GEMM (nb_conv)
// ---------------------------------------------------------------------------
__device__ __forceinline__ void pair_gemm(const u64* f, const u64* wsp, int p,
                                          float& rA, float& rB)
{
    const ulonglong2* row = (const ulonglong2*)(f + p * 32);
    u64 aE = 0ull, aO = 0ull;
    #pragma unroll
    for (int c2 = 0; c2 < 16; ++c2) {
        ulonglong2 q = row[c2];
        fma2(aE, q.x, wsp[2 * c2]);
        fma2(aO, q.y, wsp[2 * c2 + 1]);
    }
    float2 e = unpack2(aE), o = unpack2(aO);
    rA = e.x + o.x;
    rB = e.y + o.y;
}

// ---------------------------------------------------------------------------
// neighbor taps: FMA pipeline, coalesced fp16x2 atomics
// ---------------------------------------------------------------------------
template <typename T>
__global__ __launch_bounds__(256)
void nb_conv(const T* __restrict__ x, const float* __restrict__ W,
             int kstride, int hoff, __half* __restrict__ acc, int n)
{
    __shared__ u64 ft[8 * 512];
    const int j   = blockIdx.x / BLKSEG;
    const int bis = blockIdx.x % BLKSEG;
    const int cnt = g_kcnt[j];
    if (bis * 256 >= cnt) return;

    const int k = (j < 13) ? j : j + 1;
    const float* Wk = W + (size_t)k * kstride + hoff;

    const int lane = threadIdx.x & 31;
    const int warp = threadIdx.x >> 5;

    u64 wsp[32];
    #pragma unroll
    for (int c = 0; c < 32; ++c) wsp[c] = splat2(__ldg(Wk + c * 32 + lane));

    const int eidx = bis * 256 + warp * 32 + lane;
    int2 e = (eidx < cnt) ? __ldg(&g_rb[j * SEG + eidx]) : make_int2(n, 0);

    u64* f = ft + warp * 512;
    #pragma unroll 4
    for (int p = 0; p < 16; ++p) {
        int uA = __shfl_sync(0xffffffffu, e.y, 2 * p);
        int uB = __shfl_sync(0xffffffffu, e.y, 2 * p + 1);
        f[p * 32 + lane] = pack2(loadf(x + (size_t)uA * 32 + lane),
                                 loadf(x + (size_t)uB * 32 + lane));
    }
    __syncwarp();

    #pragma unroll 2
    for (int p = 0; p < 16; ++p) {
        float rA, rB;
        pair_gemm(f, wsp, p, rA, rB);
        int vA = __shfl_sync(0xffffffffu, e.x, 2 * p);
        int vB = __shfl_sync(0xffffffffu, e.x, 2 * p + 1);
        float pA = __shfl_xor_sync(0xffffffffu, rA, 1);
        float pB = __shfl_xor_sync(0xffffffffu, rB, 1);
        unsigned hv;
        int v;
        if ((lane & 1) == 0) { hv = cvt_h2(rA, pA); v = vA; }
        else                 { hv = cvt_h2(pB, rB); v = vB; }
        redadd_h2(acc + (size_t)v * 32 + (lane & ~1), hv);
    }
}

// ---------------------------------------------------------------------------
// epilogue via HMMA, acc rows PRELOADED up-front (predicated on g_flag):
//   conv = [flag? acc : 0] + Wc0^T x0 (+ Wc1^T x1 for MODE 2)
//   MODE 0: y = relu(bn(conv)); 1: +res before relu; 2: +xred(cat(x0,x1)) after
// ---------------------------------------------------------------------------
template <int MODE, typename T0, typename TOUT>
__global__ __launch_bounds__(128)
void epi(const __half* __restrict__ acc, const float* __restrict__ bnp,
         const T0* __restrict__ x0, const float* __restrict__ Wc0,
         const __half* __restrict__ x1, const float* __restrict__ Wc1,
         const float* __restrict__ res,
         TOUT* __restrict__ out, int n)
{
    __shared__ __align__(16) char xsm[4 * 64 * ROWB];
    __shared__ float ssm[32], bsm[32];

    const int tid  = threadIdx.x;
    const int lane = tid & 31;
    const int warp = tid >> 5;
    const int g = lane >> 2, t = lane & 3;

    if (tid < 32) {
        float s = __ldg(bnp + tid) * rsqrtf(__ldg(bnp + 96 + tid) + 1e-3f);
        ssm[tid] = s;
        bsm[tid] = __ldg(bnp + 32 + tid) - __ldg(bnp + 64 + tid) * s;
    }
    __syncthreads();

    const int base = (blockIdx.x * 4 + warp) * 32;
    if (base >= n) return;

    // per-warp flag mask
    unsigned fmask;
    {
        int vox = base + lane;
        bool f = (vox < n) && (g_flag[vox] != 0);
        fmask = __ballot_sync(0xffffffffu, f);
    }

    // ---- hoisted predicated acc preloads (MLP) ----
    unsigned accbits[16];
    #pragma unroll
    for (int mt = 0; mt < 2; ++mt) {
        #pragma unroll
        for (int rw = 0; rw < 2; ++rw) {
            int row = mt * 16 + 8 * rw + g;
            int vv = base + row;
            int u = (vv < n) ? vv : 0;
            bool has = (fmask >> row) & 1;
            #pragma unroll
            for (int nb = 0; nb < 4; ++nb) {
                unsigned b = 0;
                if (has)
                    b = *(const unsigned*)(acc + (size_t)u * 32 + nb * 8 + 2 * t);
                accbits[(mt * 2 + rw) * 4 + nb] = b;
            }
        }
    }

    char* x0b = xsm + warp * (64 * ROWB);
    char* x1b = x0b + 32 * ROWB;

    if (base + 32 <= n) {
        stage_tile(x0b, x0, base, lane);
        if (MODE == 2) stage_tile(x1b, x1, base, lane);
    } else {
        int vox = base + lane;
        int uu = (vox < n) ? vox : 0;
        stage_row(x0b, lane, x0 + (size_t)uu * 32);
        if (MODE == 2) stage_row(x1b, lane, x1 + (size_t)uu * 32);
    }
    __syncwarp();

    unsigned bf0[4][2][2];
    buildB(bf0, Wc0, lane);
    unsigned bf1[4][2][2];
    if (MODE == 2) buildB(bf1, Wc1, lane);

    #pragma unroll
    for (int mt = 0; mt < 2; ++mt) {
        unsigned a0[2][4];
        ldmA(a0[0], x0b, mt, 0, lane);
        ldmA(a0[1], x0b, mt, 1, lane);
        float d[4][4] = {};
        #pragma unroll
        for (int nb = 0; nb < 4; ++nb) {
            mma16816(d[nb], a0[0], bf0[nb][0]);
            mma16816(d[nb], a0[1], bf0[nb][1]);
        }
        if (MODE == 2) {
            unsigned a1[2][4];
            ldmA(a1[0], x1b, mt, 0, lane);
            ldmA(a1[1], x1b, mt, 1, lane);
            #pragma unroll
            for (int nb = 0; nb < 4; ++nb) {
                mma16816(d[nb], a1[0], bf1[nb][0]);
                mma16816(d[nb], a1[1], bf1[nb][1]);
            }
        }

        int v1 = base + mt * 16 + g;
        int v2 = v1 + 8;
        int u1 = (v1 < n) ? v1 : 0;
        int u2 = (v2 < n) ? v2 : 0;

        #pragma unroll
        for (int nb = 0; nb < 4; ++nb) {
            int c0 = nb * 8 + 2 * t;
            float s0 = ssm[c0], s1 = ssm[c0 + 1];
            float b0 = bsm[c0], b1 = bsm[c0 + 1];

            #pragma unroll
            for (int rw = 0; rw < 2; ++rw) {
                int u = rw ? u2 : u1;
                int v = rw ? v2 : v1;
                float dv0 = d[nb][rw * 2], dv1 = d[nb][rw * 2 + 1];
                float2 a2 = h2f(accbits[(mt * 2 + rw) * 4 + nb]);
                float y0 = (a2.x + dv0) * s0 + b0;
                float y1 = (a2.y + dv1) * s1 + b1;
                if (MODE == 1) {
                    float2 rr = __ldg((const float2*)(res + (size_t)u * 32 + c0));
                    y0 += rr.x; y1 += rr.y;
                }
                y0 = fmaxf(y0, 0.0f);
                y1 = fmaxf(y1, 0.0f);
                if (MODE == 2) {
                    if (nb < 2) {
                        float4 q = __ldg((const float4*)((const float*)x0 +
                                         (size_t)u * 32 + 2 * c0));
                        y0 += q.x + q.y;
                        y1 += q.z + q.w;
                    } else {
                        const __half2* hp = (const __half2*)(x1 +
                                            (size_t)u * 32 + (2 * c0 - 32));
                        float2 qa = __half22float2(__ldg(hp));
                        float2 qb = __half22float2(__ldg(hp + 1));
                        y0 += qa.x + qa.y;
                        y1 += qb.x + qb.y;
                    }
                }
                if (v < n) storepair(out + (size_t)v * 32 + c0, y0, y1);
            }
        }
    }
}

// ---------------------------------------------------------------------------
extern "C" void kernel_launch(void* const* d_in, const int* in_sizes, int n_in,
                              void* d_out, int out_size)
{
    const float* lat  = (const float*)d_in[0];
    const float* bot  = (const float*)d_in[1];
    const float* Wt1  = (const float*)d_in[2];
    const float* bnt1 = (const float*)d_in[3];
    const float* Wt2  = (const float*)d_in[4];
    const float* bnt2 = (const float*)d_in[5];
    const float* Wm   = (const float*)d_in[6];
    const float* bnm  = (const float*)d_in[7];
    const float* Wi   = (const float*)d_in[8];
    const float* bni  = (const float*)d_in[9];
    const int*   nbr  = (const int*)d_in[10];

    const int n = in_sizes[0] / NC;

    __half *accb, *h1, *h2, *h3;
    int* kcnt;
    cudaGetSymbolAddress((void**)&accb, g_acc);
    cudaGetSymbolAddress((void**)&h1, g_h1);
    cudaGetSymbolAddress((void**)&h2, g_h2);
    cudaGetSymbolAddress((void**)&h3, g_h3);
    cudaGetSymbolAddress((void**)&kcnt, g_kcnt);

    __half* a1 = accb;
    __half* a2 = accb + 1 * ASTRIDE;
    __half* a3 = accb + 2 * ASTRIDE;
    __half* a4 = accb + 3 * ASTRIDE;

    static cudaStream_t s1 = nullptr, s2 = nullptr;
    static cudaEvent_t e0 = nullptr, eB = nullptr, e2 = nullptr;
    static cudaEvent_t em1 = nullptr, em2 = nullptr, em3 = nullptr, em4 = nullptr;
    if (!s1) {
        cudaStreamCreateWithFlags(&s1, cudaStreamNonBlocking);
        cudaStreamCreateWithFlags(&s2, cudaStreamNonBlocking);
        cudaEventCreateWithFlags(&e0, cudaEventDisableTiming);
        cudaEventCreateWithFlags(&eB, cudaEventDisableTiming);
        cudaEventCreateWithFlags(&e2, cudaEventDisableTiming);
        cudaEventCreateWithFlags(&em1, cudaEventDisableTiming);
        cudaEventCreateWithFlags(&em2, cudaEventDisableTiming);
        cudaEventCreateWithFlags(&em3, cudaEventDisableTiming);
        cudaEventCreateWithFlags(&em4, cudaEventDisableTiming);
    }

    const int gridC = (n + 255) / 256;
    const int gridE = (n + 127) / 128;
    const int gridN = NBK * BLKSEG;

    cudaMemsetAsync(kcnt, 0, 32 * sizeof(int), 0);
    cudaEventRecord(e0, 0);
    cudaStreamWaitEvent(s1, e0, 0);
    cudaMemsetAsync(a1, 0, ACCBYTES, s1); cudaEventRecord(em1, s1);
    cudaMemsetAsync(a3, 0, ACCBYTES, s1); cudaEventRecord(em3, s1);
    cudaMemsetAsync(a2, 0, ACCBYTES, s1); cudaEventRecord(em2, s1);
    cudaMemsetAsync(a4, 0, ACCBYTES, s1); cudaEventRecord(em4, s1);

    build_rb<<<gridC, 256>>>(nbr, n);
    cudaEventRecord(eB, 0);

    // fork: conv_m's bot-half neighbor pass overlaps conv1/conv2
    cudaStreamWaitEvent(s2, eB, 0);
    cudaStreamWaitEvent(s2, em3, 0);
    nb_conv<float><<<gridN, 256, 0, s2>>>(bot, Wm, 2048, 0, a3, n);
    cudaEventRecord(e2, s2);

    // conv1
    cudaStreamWaitEvent(0, em1, 0);
    nb_conv<float><<<gridN, 256>>>(lat, Wt1, 1024, 0, a1, n);
    epi<0, float, __half><<<gridE, 128>>>(a1, bnt1, lat, Wt1 + 13 * 1024,
                                          nullptr, nullptr, nullptr, h1, n);

    // conv2 (residual = lat fp32)
    cudaStreamWaitEvent(0, em2, 0);
    nb_conv<__half><<<gridN, 256>>>(h1, Wt2, 1024, 0, a2, n);
    epi<1, __half, __half><<<gridE, 128>>>(a2, bnt2, h1, Wt2 + 13 * 1024,
                                           nullptr, nullptr, lat, h2, n);

    // conv_m
    nb_conv<__half><<<gridN, 256>>>(h2, Wm, 2048, 1024, a3, n);
    cudaStreamWaitEvent(0, e2, 0);
    epi<2, float, __half><<<gridE, 128>>>(a3, bnm, bot, Wm + 13 * 2048,
                                          h2, Wm + 13 * 2048 + 1024, nullptr, h3, n);

    // conv_inv
    cudaStreamWaitEvent(0, em4, 0);
    nb_conv<__half><<<gridN, 256>>>(h3, Wi, 1024, 0, a4, n);
    epi<0, __half, float><<<gridE, 128>>>(a4, bni, h3, Wi + 13 * 1024,
                                          nullptr, nullptr, nullptr, (float*)d_out, n);
}

// round 17
// speedup vs baseline: 1.2035x; 1.0234x over previous
#include <cuda_runtime.h>
#include <cuda_fp16.h>

// ---------------------------------------------------------------------------
// UNetV2 on GB300 (R17 = R16 + smem-staged res (MODE1) + smem xred (MODE2)):
//  - nb_conv: FMA f32x2 gather-GEMM, coalesced fp16x2 atomics
//  - epi: predicated hoisted acc preloads, flat coalesced tile staging,
//    HMMA center tap; res/xred served from smem tiles (conflict-free ROWB=80)
// ---------------------------------------------------------------------------

#define MAXN 500000
#define NC   32
#define SEG  16384
#define NBK  26
#define BLKSEG 64
#define ASTRIDE ((size_t)(MAXN + 1) * NC)
#define ACCBYTES (ASTRIDE * sizeof(__half))
#define ROWB 80

static __device__ __half g_acc[4 * ASTRIDE];
static __device__ __half g_h1[MAXN * NC];
static __device__ __half g_h2[MAXN * NC];
static __device__ __half g_h3[MAXN * NC];
static __device__ int2   g_rb[NBK * SEG];
static __device__ int    g_kcnt[32];
static __device__ unsigned char g_flag[MAXN + 256];

typedef unsigned long long u64;

__device__ __forceinline__ u64 splat2(float a) {
    u64 r; asm("mov.b64 %0, {%1, %1};" : "=l"(r) : "f"(a)); return r;
}
__device__ __forceinline__ u64 pack2(float a, float b) {
    u64 r; asm("mov.b64 %0, {%1, %2};" : "=l"(r) : "f"(a), "f"(b)); return r;
}
__device__ __forceinline__ void fma2(u64& d, u64 a, u64 b) {
    asm("fma.rn.f32x2 %0, %1, %2, %3;" : "=l"(d) : "l"(a), "l"(b), "l"(d));
}
__device__ __forceinline__ float2 unpack2(u64 a) {
    float2 r; asm("mov.b64 {%0, %1}, %2;" : "=f"(r.x), "=f"(r.y) : "l"(a)); return r;
}
__device__ __forceinline__ unsigned cvt_h2(float lo, float hi) {
    unsigned r;
    asm("cvt.rn.f16x2.f32 %0, %1, %2;" : "=r"(r) : "f"(hi), "f"(lo));
    return r;
}
__device__ __forceinline__ float2 h2f(unsigned u) {
    return __half22float2(*(__half2*)&u);
}
__device__ __forceinline__ void redadd_h2(__half* p, unsigned hv) {
    asm volatile("red.global.add.noftz.f16x2 [%0], %1;" :: "l"(p), "r"(hv) : "memory");
}
__device__ __forceinline__ float loadf(const float* p)  { return __ldg(p); }
__device__ __forceinline__ float loadf(const __half* p) { return __half2float(__ldg(p)); }
__device__ __forceinline__ void storepair(float* p, float y0, float y1) {
    *(float2*)p = make_float2(y0, y1);
}
__device__ __forceinline__ void storepair(__half* p, float y0, float y1) {
    *(__half2*)p = __floats2half2_rn(y0, y1);
}

// ---------------------------------------------------------------------------
// smem tile staging
// ---------------------------------------------------------------------------
__device__ __forceinline__ void stage_row(char* wbase, int r, const __half* row) {
    const uint4* s = (const uint4*)row;
    int sw = (r >> 3) & 3;
    char* rb = wbase + r * ROWB;
    #pragma unroll
    for (int c = 0; c < 4; ++c)
        *(uint4*)(rb + ((c ^ sw) << 4)) = __ldg(s + c);
}
__device__ __forceinline__ void stage_row(char* wbase, int r, const float* row) {
    const float4* s = (const float4*)row;
    int sw = (r >> 3) & 3;
    char* rb = wbase + r * ROWB;
    #pragma unroll
    for (int c = 0; c < 4; ++c) {
        float4 f0 = __ldg(s + 2 * c);
        float4 f1 = __ldg(s + 2 * c + 1);
        uint4 v;
        v.x = cvt_h2(f0.x, f0.y); v.y = cvt_h2(f0.z, f0.w);
        v.z = cvt_h2(f1.x, f1.y); v.w = cvt_h2(f1.z, f1.w);
        *(uint4*)(rb + ((c ^ sw) << 4)) = v;
    }
}
__device__ __forceinline__ void stage_tile(char* wbase, const __half* x,
                                           int base, int lane) {
    const uint4* src = (const uint4*)(x + (size_t)base * 32);
    #pragma unroll
    for (int k2 = 0; k2 < 4; ++k2) {
        int idx = k2 * 32 + lane;
        uint4 v = __ldg(src + idx);
        int row = idx >> 2;
        int cw  = idx & 3;
        int sw  = (row >> 3) & 3;
        *(uint4*)(wbase + row * ROWB + ((cw ^ sw) << 4)) = v;
    }
}
__device__ __forceinline__ void stage_tile(char* wbase, const float* x,
                                           int base, int lane) {
    const float4* src = (const float4*)(x + (size_t)base * 32);
    #pragma unroll
    for (int k2 = 0; k2 < 8; ++k2) {
        int idx = k2 * 32 + lane;
        float4 f = __ldg(src + idx);
        uint2 v = make_uint2(cvt_h2(f.x, f.y), cvt_h2(f.z, f.w));
        int row = idx >> 3;
        int q   = idx & 7;
        int cw  = q >> 1;
        int h   = q & 1;
        int sw  = (row >> 3) & 3;
        *(uint2*)(wbase + row * ROWB + ((cw ^ sw) << 4) + h * 8) = v;
    }
}

__device__ __forceinline__ void ldmA(unsigned a[4], const char* wbase, int mt,
                                     int kb, int lane) {
    int r  = mt * 16 + (lane & 15);
    int lc = 2 * kb + (lane >> 4);
    unsigned addr = (unsigned)__cvta_generic_to_shared(
        wbase + r * ROWB + ((lc ^ ((r >> 3) & 3)) << 4));
    asm volatile("ldmatrix.sync.aligned.m8n8.x4.shared.b16 {%0,%1,%2,%3}, [%4];"
                 : "=r"(a[0]), "=r"(a[1]), "=r"(a[2]), "=r"(a[3]) : "r"(addr));
}
__device__ __forceinline__ void mma16816(float d[4], const unsigned a[4],
                                         const unsigned b[2]) {
    asm volatile(
        "mma.sync.aligned.m16n8k16.row.col.f32.f16.f16.f32 "
        "{%0,%1,%2,%3},{%4,%5,%6,%7},{%8,%9},{%0,%1,%2,%3};"
        : "+f"(d[0]), "+f"(d[1]), "+f"(d[2]), "+f"(d[3])
        : "r"(a[0]), "r"(a[1]), "r"(a[2]), "r"(a[3]), "r"(b[0]), "r"(b[1]));
}
__device__ __forceinline__ void buildB(unsigned bf[4][2][2], const float* Wk,
                                       int lane) {
    int g = lane >> 2, t = lane & 3;
    #pragma unroll
    for (int nb = 0; nb < 4; ++nb) {
        int nn = nb * 8 + g;
        #pragma unroll
        for (int kb = 0; kb < 2; ++kb) {
            int k0 = 16 * kb + 2 * t;
            bf[nb][kb][0] = cvt_h2(__ldg(Wk + k0 * 32 + nn),
                                   __ldg(Wk + (k0 + 1) * 32 + nn));
            bf[nb][kb][1] = cvt_h2(__ldg(Wk + (k0 + 8) * 32 + nn),
                                   __ldg(Wk + (k0 + 9) * 32 + nn));
        }
    }
}

// ---------------------------------------------------------------------------
__global__ __launch_bounds__(256)
void build_rb(const int* __restrict__ nbr, int n)
{
    __shared__ int nsh[256 * 27];
    const int tid  = threadIdx.x;
    const int lane = tid & 31;
    const long long base = (long long)blockIdx.x * 256;

    for (int i = tid; i < 256 * 27; i += 256) {
        long long g = base * 27 + i;
        nsh[i] = (g < (long long)n * 27) ? nbr[g] : n;
    }
    __syncthreads();

    const int v = (int)(base + tid);
    const bool live = v < n;
    bool anyn = false;

    #pragma unroll 1
    for (int j = 0; j < NBK; ++j) {
        int k = (j < 13) ? j : j + 1;
        int u = nsh[tid * 27 + k];
        bool want = live && ((unsigned)u < (unsigned)n);
        anyn |= want;
        unsigned m = __ballot_sync(0xffffffffu, want);
        int rank = __popc(m & ((1u << lane) - 1));
        int leader = (m != 0u) ? (__ffs(m) - 1) : 0;
        int bp = 0;
        if (m != 0u && lane == leader) bp = atomicAdd(&g_kcnt[j], __popc(m));
        bp = __shfl_sync(0xffffffffu, bp, leader);
        int pos = bp + rank;
        if (want && pos < SEG) g_rb[j * SEG + pos] = make_int2(v, u);
    }

    if (live) g_flag[v] = anyn ? 1 : 0;
}

// ---------------------------------------------------------------------------
__device__ __forceinline__ void pair_gemm(const u64* f, const u64* wsp, int p,
                                          float& rA, float& rB)
{
    const ulonglong2* row = (const ulonglong2*)(f + p * 32);
    u64 aE = 0ull, aO = 0ull;
    #pragma unroll
    for (int c2 = 0; c2 < 16; ++c2) {
        ulonglong2 q = row[c2];
        fma2(aE, q.x, wsp[2 * c2]);
        fma2(aO, q.y, wsp[2 * c2 + 1]);
    }
    float2 e = unpack2(aE), o = unpack2(aO);
    rA = e.x + o.x;
    rB = e.y + o.y;
}

// ---------------------------------------------------------------------------
// neighbor taps: FMA pipeline, coalesced fp16x2 atomics
// ---------------------------------------------------------------------------
template <typename T>
__global__ __launch_bounds__(256)
void nb_conv(const T* __restrict__ x, const float* __restrict__ W,
             int kstride, int hoff, __half* __restrict__ acc, int n)
{
    __shared__ u64 ft[8 * 512];
    const int j   = blockIdx.x / BLKSEG;
    const int bis = blockIdx.x % BLKSEG;
    const int cnt = g_kcnt[j];
    if (bis * 256 >= cnt) return;

    const int k = (j < 13) ? j : j + 1;
    const float* Wk = W + (size_t)k * kstride + hoff;

    const int lane = threadIdx.x & 31;
    const int warp = threadIdx.x >> 5;

    u64 wsp[32];
    #pragma unroll
    for (int c = 0; c < 32; ++c) wsp[c] = splat2(__ldg(Wk + c * 32 + lane));

    const int eidx = bis * 256 + warp * 32 + lane;
    int2 e = (eidx < cnt) ? __ldg(&g_rb[j * SEG + eidx]) : make_int2(n, 0);

    u64* f = ft + warp * 512;
    #pragma unroll 8
    for (int p = 0; p < 16; ++p) {
        int uA = __shfl_sync(0xffffffffu, e.y, 2 * p);
        int uB = __shfl_sync(0xffffffffu, e.y, 2 * p + 1);
        f[p * 32 + lane] = pack2(loadf(x + (size_t)uA * 32 + lane),
                                 loadf(x + (size_t)uB * 32 + lane));
    }
    __syncwarp();

    #pragma unroll 2
    for (int p = 0; p < 16; ++p) {
        float rA, rB;
        pair_gemm(f, wsp, p, rA, rB);
        int vA = __shfl_sync(0xffffffffu, e.x, 2 * p);
        int vB = __shfl_sync(0xffffffffu, e.x, 2 * p + 1);
        float pA = __shfl_xor_sync(0xffffffffu, rA, 1);
        float pB = __shfl_xor_sync(0xffffffffu, rB, 1);
        unsigned hv;
        int v;
        if ((lane & 1) == 0) { hv = cvt_h2(rA, pA); v = vA; }
        else                 { hv = cvt_h2(pB, rB); v = vB; }
        redadd_h2(acc + (size_t)v * 32 + (lane & ~1), hv);
    }
}

// ---------------------------------------------------------------------------
// epilogue via HMMA, hoisted predicated acc preloads, flat tile staging:
//   conv = [flag? acc : 0] + Wc0^T x0 (+ Wc1^T x1 for MODE 2)
//   MODE 0: y = relu(bn(conv))
//   MODE 1: y = relu(bn(conv) + res)        [res staged fp16 in x1b span]
//   MODE 2: y = relu(bn(conv)) + xred(cat)  [xred read from smem tiles]
// ---------------------------------------------------------------------------
template <int MODE, typename T0, typename TOUT>
__global__ __launch_bounds__(128)
void epi(const __half* __restrict__ acc, const float* __restrict__ bnp,
         const T0* __restrict__ x0, const float* __restrict__ Wc0,
         const __half* __restrict__ x1, const float* __restrict__ Wc1,
         const float* __restrict__ res,
         TOUT* __restrict__ out, int n)
{
    __shared__ __align__(16) char xsm[4 * 64 * ROWB];
    __shared__ float ssm[32], bsm[32];

    const int tid  = threadIdx.x;
    const int lane = tid & 31;
    const int warp = tid >> 5;
    const int g = lane >> 2, t = lane & 3;

    if (tid < 32) {
        float s = __ldg(bnp + tid) * rsqrtf(__ldg(bnp + 96 + tid) + 1e-3f);
        ssm[tid] = s;
        bsm[tid] = __ldg(bnp + 32 + tid) - __ldg(bnp + 64 + tid) * s;
    }
    __syncthreads();

    const int base = (blockIdx.x * 4 + warp) * 32;
    if (base >= n) return;

    unsigned fmask;
    {
        int vox = base + lane;
        bool f = (vox < n) && (g_flag[vox] != 0);
        fmask = __ballot_sync(0xffffffffu, f);
    }

    // hoisted predicated acc preloads (MLP)
    unsigned accbits[16];
    #pragma unroll
    for (int mt = 0; mt < 2; ++mt) {
        #pragma unroll
        for (int rw = 0; rw < 2; ++rw) {
            int row = mt * 16 + 8 * rw + g;
            int vv = base + row;
            int u = (vv < n) ? vv : 0;
            bool has = (fmask >> row) & 1;
            #pragma unroll
            for (int nb = 0; nb < 4; ++nb) {
                unsigned b = 0;
                if (has)
                    b = *(const unsigned*)(acc + (size_t)u * 32 + nb * 8 + 2 * t);
                accbits[(mt * 2 + rw) * 4 + nb] = b;
            }
        }
    }

    char* x0b = xsm + warp * (64 * ROWB);
    char* x1b = x0b + 32 * ROWB;

    if (base + 32 <= n) {
        stage_tile(x0b, x0, base, lane);
        if (MODE == 2) stage_tile(x1b, x1, base, lane);
        if (MODE == 1) stage_tile(x1b, res, base, lane);
    } else {
        int vox = base + lane;
        int uu = (vox < n) ? vox : 0;
        stage_row(x0b, lane, x0 + (size_t)uu * 32);
        if (MODE == 2) stage_row(x1b, lane, x1 + (size_t)uu * 32);
        if (MODE == 1) stage_row(x1b, lane, res + (size_t)uu * 32);
    }
    __syncwarp();

    unsigned bf0[4][2][2];
    buildB(bf0, Wc0, lane);
    unsigned bf1[4][2][2];
    if (MODE == 2) buildB(bf1, Wc1, lane);

    #pragma unroll
    for (int mt = 0; mt < 2; ++mt) {
        unsigned a0[2][4];
        ldmA(a0[0], x0b, mt, 0, lane);
        ldmA(a0[1], x0b, mt, 1, lane);
        float d[4][4] = {};
        #pragma unroll
        for (int nb = 0; nb < 4; ++nb) {
            mma16816(d[nb], a0[0], bf0[nb][0]);
            mma16816(d[nb], a0[1], bf0[nb][1]);
        }
        if (MODE == 2) {
            unsigned a1[2][4];
            ldmA(a1[0], x1b, mt, 0, lane);
            ldmA(a1[1], x1b, mt, 1, lane);
            #pragma unroll
            for (int nb = 0; nb < 4; ++nb) {
                mma16816(d[nb], a1[0], bf1[nb][0]);
                mma16816(d[nb], a1[1], bf1[nb][1]);
            }
        }

        int v1 = base + mt * 16 + g;
        int v2 = v1 + 8;

        #pragma unroll
        for (int nb = 0; nb < 4; ++nb) {
            int c0 = nb * 8 + 2 * t;
            float s0 = ssm[c0], s1 = ssm[c0 + 1];
            float b0 = bsm[c0], b1 = bsm[c0 + 1];

            #pragma unroll
            for (int rw = 0; rw < 2; ++rw) {
                int v = rw ? v2 : v1;
                int r = mt * 16 + 8 * rw + g;           // local tile row
                int sw2 = (r >> 3) & 3;
                float dv0 = d[nb][rw * 2], dv1 = d[nb][rw * 2 + 1];
                float2 a2 = h2f(accbits[(mt * 2 + rw) * 4 + nb]);
                float y0 = (a2.x + dv0) * s0 + b0;
                float y1 = (a2.y + dv1) * s1 + b1;
                if (MODE == 1) {
                    unsigned rr = *(const unsigned*)(x1b + r * ROWB +
                                   ((nb ^ sw2) << 4) + 4 * t);
                    float2 rv = h2f(rr);
                    y0 += rv.x; y1 += rv.y;
                }
                y0 = fmaxf(y0, 0.0f);
                y1 = fmaxf(y1, 0.0f);
                if (MODE == 2) {
                    // xred from smem tiles: channels 2c0..2c0+3 of cat(x0,x1)
                    int nbl = (nb < 2) ? nb : nb - 2;
                    const char* xb = (nb < 2) ? x0b : x1b;
                    int cw = 2 * nbl + (t >> 1);
                    uint2 q = *(const uint2*)(xb + r * ROWB +
                              ((cw ^ sw2) << 4) + 8 * (t & 1));
                    float2 qa = h2f(q.x);
                    float2 qb = h2f(q.y);
                    y0 += qa.x + qa.y;
                    y1 += qb.x + qb.y;
                }
                if (v < n) storepair(out + (size_t)v * 32 + c0, y0, y1);
            }
        }
    }
}

// ---------------------------------------------------------------------------
extern "C" void kernel_launch(void* const* d_in, const int* in_sizes, int n_in,
                              void* d_out, int out_size)
{
    const float* lat  = (const float*)d_in[0];
    const float* bot  = (const float*)d_in[1];
    const float* Wt1  = (const float*)d_in[2];
    const float* bnt1 = (const float*)d_in[3];
    const float* Wt2  = (const float*)d_in[4];
    const float* bnt2 = (const float*)d_in[5];
    const float* Wm   = (const float*)d_in[6];
    const float* bnm  = (const float*)d_in[7];
    const float* Wi   = (const float*)d_in[8];
    const float* bni  = (const float*)d_in[9];
    const int*   nbr  = (const int*)d_in[10];

    const int n = in_sizes[0] / NC;

    __half *accb, *h1, *h2, *h3;
    int* kcnt;
    cudaGetSymbolAddress((void**)&accb, g_acc);
    cudaGetSymbolAddress((void**)&h1, g_h1);
    cudaGetSymbolAddress((void**)&h2, g_h2);
    cudaGetSymbolAddress((void**)&h3, g_h3);
    cudaGetSymbolAddress((void**)&kcnt, g_kcnt);

    __half* a1 = accb;
    __half* a2 = accb + 1 * ASTRIDE;
    __half* a3 = accb + 2 * ASTRIDE;
    __half* a4 = accb + 3 * ASTRIDE;

    static cudaStream_t s1 = nullptr, s2 = nullptr;
    static cudaEvent_t e0 = nullptr, eB = nullptr, e2 = nullptr;
    static cudaEvent_t em1 = nullptr, em2 = nullptr, em3 = nullptr, em4 = nullptr;
    if (!s1) {
        cudaStreamCreateWithFlags(&s1, cudaStreamNonBlocking);
        cudaStreamCreateWithFlags(&s2, cudaStreamNonBlocking);
        cudaEventCreateWithFlags(&e0, cudaEventDisableTiming);
        cudaEventCreateWithFlags(&eB, cudaEventDisableTiming);
        cudaEventCreateWithFlags(&e2, cudaEventDisableTiming);
        cudaEventCreateWithFlags(&em1, cudaEventDisableTiming);
        cudaEventCreateWithFlags(&em2, cudaEventDisableTiming);
        cudaEventCreateWithFlags(&em3, cudaEventDisableTiming);
        cudaEventCreateWithFlags(&em4, cudaEventDisableTiming);
    }

    const int gridC = (n + 255) / 256;
    const int gridE = (n + 127) / 128;
    const int gridN = NBK * BLKSEG;

    cudaMemsetAsync(kcnt, 0, 32 * sizeof(int), 0);
    cudaEventRecord(e0, 0);
    cudaStreamWaitEvent(s1, e0, 0);
    cudaMemsetAsync(a1, 0, ACCBYTES, s1); cudaEventRecord(em1, s1);
    cudaMemsetAsync(a3, 0, ACCBYTES, s1); cudaEventRecord(em3, s1);
    cudaMemsetAsync(a2, 0, ACCBYTES, s1); cudaEventRecord(em2, s1);
    cudaMemsetAsync(a4, 0, ACCBYTES, s1); cudaEventRecord(em4, s1);

    build_rb<<<gridC, 256>>>(nbr, n);
    cudaEventRecord(eB, 0);

    // fork: conv_m's bot-half neighbor pass overlaps conv1/conv2
    cudaStreamWaitEvent(s2, eB, 0);
    cudaStreamWaitEvent(s2, em3, 0);
    nb_conv<float><<<gridN, 256, 0, s2>>>(bot, Wm, 2048, 0, a3, n);
    cudaEventRecord(e2, s2);

    // conv1
    cudaStreamWaitEvent(0, em1, 0);
    nb_conv<float><<<gridN, 256>>>(lat, Wt1, 1024, 0, a1, n);
    epi<0, float, __half><<<gridE, 128>>>(a1, bnt1, lat, Wt1 + 13 * 1024,
                                          nullptr, nullptr, nullptr, h1, n);

    // conv2 (residual = lat, staged fp16 through smem)
    cudaStreamWaitEvent(0, em2, 0);
    nb_conv<__half><<<gridN, 256>>>(h1, Wt2, 1024, 0, a2, n);
    epi<1, __half, __half><<<gridE, 128>>>(a2, bnt2, h1, Wt2 + 13 * 1024,
                                           nullptr, nullptr, lat, h2, n);

    // conv_m
    nb_conv<__half><<<gridN, 256>>>(h2, Wm, 2048, 1024, a3, n);
    cudaStreamWaitEvent(0, e2, 0);
    epi<2, float, __half><<<gridE, 128>>>(a3, bnm, bot, Wm + 13 * 2048,
                                          h2, Wm + 13 * 2048 + 1024, nullptr, h3, n);

    // conv_inv
    cudaStreamWaitEvent(0, em4, 0);
    nb_conv<__half><<<gridN, 256>>>(h3, Wi, 1024, 0, a4, n);
    epi<0, __half, float><<<gridE, 128>>>(a4, bni, h3, Wi + 13 * 1024,
                                          nullptr, nullptr, nullptr, (float*)d_out, n);
}